// round 14
// baseline (speedup 1.0000x reference)
#include <cuda_runtime.h>
#include <math.h>
#include <stdint.h>

#define N_NODES 50000
#define N_EDGES 800000
#define H1 128
#define F_NODE 1363
#define F_STRUCT 83
#define F_ESM 1280
#define NODE_IN 339
#define H0P 96
#define NLAYERS 4

// ---------------- scratch ----------------
__device__ float g_h[N_NODES * H1];
__device__ float g_PQ[N_NODES * 256];
__device__ float g_agg[N_NODES * H1];
__device__ float g_tmp[N_NODES * H1];
__device__ float g_esmin[N_NODES * F_ESM];
__device__ float g_h0p[N_NODES * H0P];
__device__ float g_esm1[N_NODES * 256];
__device__ float g_cat[N_NODES * 192];
__device__ float g_last[N_NODES * 192];
__device__ float g_radial[N_EDGES];

__device__ __forceinline__ float siluf(float x) { return x / (1.f + __expf(-x)); }
__device__ __forceinline__ float sigmf(float x) { return 1.f / (1.f + __expf(-x)); }
__device__ __forceinline__ uint32_t f2u(float x) { return __float_as_uint(x); }

// k-rotated W layout: element (k, c) lives at k*128 + ((c/4 + 2k)%32)*4 + c%4.
// B-fragment loads (lanes t4 x g) then hit 8 distinct 16B bank-groups.
__device__ __forceinline__ int wsw(int k, int c) {
    return k * 128 + ((((c >> 2) + 2 * k) & 31) << 2) + (c & 3);
}

#define MMA8(d, a, b0, b1)                                                    \
    asm volatile(                                                             \
        "mma.sync.aligned.m16n8k8.row.col.f32.tf32.tf32.f32 "                 \
        "{%0,%1,%2,%3}, {%4,%5,%6,%7}, {%8,%9}, {%0,%1,%2,%3};"               \
        : "+f"(d[0]), "+f"(d[1]), "+f"(d[2]), "+f"(d[3])                      \
        : "r"(a[0]), "r"(a[1]), "r"(a[2]), "r"(a[3]), "r"(b0), "r"(b1))

__device__ __forceinline__ void cp_async16(uint32_t dst, const void* src, int sz) {
    asm volatile("cp.async.cg.shared.global [%0], [%1], 16, %2;"
                 :: "r"(dst), "l"(src), "r"(sz));
}
#define CP_COMMIT() asm volatile("cp.async.commit_group;")
template <int NW>
__device__ __forceinline__ void cp_wait() {
    asm volatile("cp.async.wait_group %0;" :: "n"(NW));
}

// ---------------- radial ----------------
__global__ void radial_kernel(const float* __restrict__ coords,
                              const int* __restrict__ ei,
                              float* __restrict__ radial) {
    int e = blockIdx.x * blockDim.x + threadIdx.x;
    if (e >= N_EDGES) return;
    int r = ei[e], c = ei[N_EDGES + e];
    float dx = coords[r * 3 + 0] - coords[c * 3 + 0];
    float dy = coords[r * 3 + 1] - coords[c * 3 + 1];
    float dz = coords[r * 3 + 2] - coords[c * 3 + 2];
    radial[e] = dx * dx + dy * dy + dz * dz;
}

// ---------------- copy inputs to aligned/padded buffers ----------------
__global__ void copy_inputs(const float* __restrict__ na,
                            float* __restrict__ esmd, float* __restrict__ h0p) {
    int n = blockIdx.x, t = threadIdx.x;
    const float* src = na + (size_t)n * F_NODE;
#pragma unroll
    for (int c = t; c < F_ESM; c += 256) esmd[(size_t)n * F_ESM + c] = src[F_STRUCT + c];
    if (t < H0P) h0p[(size_t)n * H0P + t] = (t < F_STRUCT) ? src[t] : 0.f;
}

// ---------------- shared tile constants ----------------
#define BKT 32
#define STAGES 3
#define AS_STRIDE 36
#define WS_SZ (BKT * 128)
#define GEMM_SMEM_OF(BM) (((BM) * AS_STRIDE + WS_SZ) * STAGES * 4)

// ---------------- async 3-stage tf32 GEMM, templated block-M ----------------
// 8 warps. BM=128: 4m x 2n (warp 32x64, NT=8). BM=64: 2m x 4n (warp 32x32, NT=4).
template <int BM, int ACT, bool RESID, bool BIAS, int NX, bool WSPLIT, bool ZAGG>
__global__ __launch_bounds__(256) void gemm_tc(
        const float* __restrict__ X, const float* __restrict__ X2,
        const float* __restrict__ X3, int ldx, int ldx3,
        const float* __restrict__ W, int ldw, int COw,
        const float* __restrict__ B,
        float* __restrict__ Y, int ldy,
        int M, int K, int KW, int CO,
        float* __restrict__ aggz) {
    constexpr int WM = BM / 32;          // warps along m (4 or 2)
    constexpr int NT = 2 * WM;           // 8-col groups per warp (8 or 4)
    constexpr int AS_SZ = BM * AS_STRIDE;
    constexpr int STAGE_SZ = AS_SZ + WS_SZ;

    extern __shared__ float smn[];
    uint32_t sm_u = (uint32_t)__cvta_generic_to_shared(smn);

    int t = threadIdx.x;
    int warp = t >> 5, lane = t & 31;
    int g = lane >> 2, t4 = lane & 3;
    int wm = warp % WM, wn = warp / WM;
    int m0 = blockIdx.x * BM, cb = blockIdx.y * 128;

    const float* Wbase = WSPLIT ? (W + (size_t)blockIdx.y * 128 * 128) : W;
    int cw = WSPLIT ? 0 : cb;

    float acc[2][NT][4];
#pragma unroll
    for (int i = 0; i < 2; i++)
#pragma unroll
        for (int nt = 0; nt < NT; nt++)
            acc[i][nt][0] = acc[i][nt][1] = acc[i][nt][2] = acc[i][nt][3] = 0.f;

    auto loadA = [&](int buf, int k0) {
        const float* Xs = X; int kb = k0, ld = ldx;
        if (NX >= 3 && k0 >= 256)      { Xs = X3; kb = k0 - 256; ld = ldx3; }
        else if (NX >= 2 && k0 >= 128) { Xs = X2; kb = k0 - 128; }
#pragma unroll
        for (int i = 0; i < BM / 32; i++) {
            int idx = t + i * 256;
            int r = idx >> 3, c4 = (idx & 7) * 4;
            uint32_t dst = sm_u + (buf * STAGE_SZ + r * AS_STRIDE + c4) * 4;
            const float* src = Xs + (size_t)(m0 + r) * ld + kb + c4;
            cp_async16(dst, src, (m0 + r < M) ? 16 : 0);
        }
    };
    auto loadW = [&](int buf, int k0) {
#pragma unroll
        for (int i = 0; i < 4; i++) {
            int idx = t + i * 256;
            int kk = idx >> 5, j = idx & 31;   // row kk, 16B chunk j
            int jr = (j + 2 * kk) & 31;        // rotated chunk slot
            uint32_t dst = sm_u + (buf * STAGE_SZ + AS_SZ + kk * 128 + jr * 4) * 4;
            const float* src = Wbase + (size_t)(k0 + kk) * ldw + cw + j * 4;
            cp_async16(dst, src, (k0 + kk < KW && cw + j * 4 < COw) ? 16 : 0);
        }
    };

    int nk = K / BKT;
    loadA(0, 0); loadW(0, 0); CP_COMMIT();
    if (nk > 1) { loadA(1, BKT); loadW(1, BKT); }
    CP_COMMIT();

    for (int ki = 0; ki < nk; ki++) {
        int buf = ki % STAGES;
        cp_wait<1>();
        __syncthreads();
        const float* A = smn + buf * STAGE_SZ;
        const float* Wb = A + AS_SZ;
#pragma unroll
        for (int ks = 0; ks < BKT; ks += 8) {
            uint32_t a[2][4];
#pragma unroll
            for (int i = 0; i < 2; i++) {
                int r = wm * 32 + i * 16 + g;
                a[i][0] = f2u(A[r * AS_STRIDE + ks + t4]);
                a[i][1] = f2u(A[(r + 8) * AS_STRIDE + ks + t4]);
                a[i][2] = f2u(A[r * AS_STRIDE + ks + t4 + 4]);
                a[i][3] = f2u(A[(r + 8) * AS_STRIDE + ks + t4 + 4]);
            }
#pragma unroll
            for (int nt = 0; nt < NT; nt++) {
                int c = wn * (NT * 8) + nt * 8 + g;
                uint32_t b0 = f2u(Wb[wsw(ks + t4, c)]);
                uint32_t b1 = f2u(Wb[wsw(ks + t4 + 4, c)]);
                MMA8(acc[0][nt], a[0], b0, b1);
                MMA8(acc[1][nt], a[1], b0, b1);
            }
        }
        __syncthreads();
        if (ki + 2 < nk) {
            int nbuf = (ki + 2) % STAGES;
            loadA(nbuf, (ki + 2) * BKT);
            loadW(nbuf, (ki + 2) * BKT);
        }
        CP_COMMIT();
    }

    // epilogue
#pragma unroll
    for (int i = 0; i < 2; i++) {
        int rA = m0 + wm * 32 + i * 16 + g;
        int rB = rA + 8;
#pragma unroll
        for (int nt = 0; nt < NT; nt++) {
            int c = cb + wn * (NT * 8) + nt * 8 + 2 * t4;
            if (c >= CO) continue;
            float b0v = 0.f, b1v = 0.f;
            if (BIAS) { b0v = B[c]; b1v = B[c + 1]; }
#pragma unroll
            for (int h2 = 0; h2 < 2; h2++) {
                int m = h2 ? rB : rA;
                if (m >= M) continue;
                float x0 = acc[i][nt][h2 * 2 + 0] + b0v;
                float x1 = acc[i][nt][h2 * 2 + 1] + b1v;
                if (ACT == 1) { x0 = siluf(x0); x1 = siluf(x1); }
                if (ACT == 2) { x0 = fmaxf(x0, 0.f); x1 = fmaxf(x1, 0.f); }
                float* yp = Y + (size_t)m * ldy + c;
                if (RESID) { float2 o = *(const float2*)yp; x0 += o.x; x1 += o.y; }
                float2 o; o.x = x0; o.y = x1;
                *(float2*)yp = o;
            }
        }
    }

    // optional: zero agg rows for this m-block (replaces cudaMemsetAsync)
    if (ZAGG && blockIdx.y == 0) {
        float4 z = {0.f, 0.f, 0.f, 0.f};
#pragma unroll
        for (int i = 0; i < BM / 8; i++) {
            int idx = t + i * 256;
            int r = idx >> 5, c4 = (idx & 31) * 4;
            if (m0 + r < M) *(float4*)(aggz + (size_t)(m0 + r) * 128 + c4) = z;
        }
    }
}

// ---------------- fused edge layer: register epilogue + register scatter ----
#define TILE_E 64
#define EDGE_TILES 4
#define N_TILES (N_EDGES / TILE_E)        // 12500
#define OFF_W2S   0                        // [128*128] rotated layout
#define OFF_HID   (128*128)                // [64][132]
#define OFF_WR    (OFF_HID + 64*132)
#define OFF_WE    (OFF_WR + 128)
#define OFF_B1    (OFF_WE + 128)
#define OFF_ATT   (OFF_B1 + 128)
#define OFF_B2    (OFF_ATT + 128)
#define OFF_RAD   (OFF_B2 + 128)
#define OFF_EA    (OFF_RAD + 64)
#define OFF_GPART (OFF_EA + 64)            // [64][2] gate partials
#define OFF_ROWS  (OFF_GPART + 128)
#define OFF_COLS  (OFF_ROWS + 64)
#define EDGE_SMEM ((OFF_COLS + 64) * 4)

__global__ __launch_bounds__(256) void edge_kernel(
        const float* __restrict__ PQ,
        const float* __restrict__ radial, const float* __restrict__ ea,
        const int* __restrict__ ei,
        const float* __restrict__ wr, const float* __restrict__ we,
        const float* __restrict__ b1,
        const float* __restrict__ W2, const float* __restrict__ B2,
        const float* __restrict__ attw, const float* __restrict__ attb,
        float* __restrict__ agg) {
    extern __shared__ float sm[];
    float* W2s  = sm + OFF_W2S;
    float* hid  = sm + OFF_HID;
    float* wr_s = sm + OFF_WR;
    float* we_s = sm + OFF_WE;
    float* b1_s = sm + OFF_B1;
    float* at_s = sm + OFF_ATT;
    float* b2_s = sm + OFF_B2;
    float* rd_s = sm + OFF_RAD;
    float* ea_s = sm + OFF_EA;
    float* gp_s = sm + OFF_GPART;
    int* rows_s = (int*)(sm + OFF_ROWS);
    int* cols_s = (int*)(sm + OFF_COLS);

    int t = threadIdx.x;
    int w = t >> 5, lane = t & 31;
    int g = lane >> 2, t4 = lane & 3;
    int eg0 = (w & 3) * 16, ng0 = (w >> 2) * 64;
    int wn = w >> 2;
    float attbv = attb[0];

    for (int idx = t; idx < 5 * 128; idx += 256) {
        int a = idx >> 7, c = idx & 127;
        float v;
        if (a == 0) v = wr[c];
        else if (a == 1) v = we[c];
        else if (a == 2) v = b1[c];
        else if (a == 3) v = attw[c];
        else v = B2[c];
        sm[OFF_WR + a * 128 + c] = v;
    }
    // stage W2 in rotated layout
    for (int idx = t; idx < 128 * 32; idx += 256) {
        int kk = idx >> 5, j = idx & 31;
        int jr = (j + 2 * kk) & 31;
        *(float4*)&W2s[kk * 128 + jr * 4] = *(const float4*)(W2 + (size_t)kk * 128 + j * 4);
    }

    for (int tt = 0; tt < EDGE_TILES; tt++) {
        int tile = blockIdx.x * EDGE_TILES + tt;
        if (tile >= N_TILES) break;
        int e0 = tile * TILE_E;

        __syncthreads();
        if (t < TILE_E) {
            rows_s[t] = ei[e0 + t];
            rd_s[t] = radial[e0 + t];
            ea_s[t] = ea[e0 + t];
        } else if (t < 2 * TILE_E) {
            cols_s[t - TILE_E] = ei[N_EDGES + e0 + (t - TILE_E)];
        }
        __syncthreads();

#pragma unroll
        for (int i = 0; i < 8; i++) {
            int idx = t + i * 256;
            int e = idx >> 5, c4 = (idx & 31) * 4;
            float4 p = *(const float4*)(PQ + (size_t)rows_s[e] * 256 + c4);
            float4 q = *(const float4*)(PQ + (size_t)cols_s[e] * 256 + 128 + c4);
            float rd = rd_s[e], eav = ea_s[e];
            float4 o;
            o.x = siluf(p.x + q.x + rd * wr_s[c4 + 0] + eav * we_s[c4 + 0] + b1_s[c4 + 0]);
            o.y = siluf(p.y + q.y + rd * wr_s[c4 + 1] + eav * we_s[c4 + 1] + b1_s[c4 + 1]);
            o.z = siluf(p.z + q.z + rd * wr_s[c4 + 2] + eav * we_s[c4 + 2] + b1_s[c4 + 2]);
            o.w = siluf(p.w + q.w + rd * wr_s[c4 + 3] + eav * we_s[c4 + 3] + b1_s[c4 + 3]);
            *(float4*)&hid[e * 132 + c4] = o;
        }
        __syncthreads();

        float acc[8][4];
#pragma unroll
        for (int nt = 0; nt < 8; nt++) { acc[nt][0] = acc[nt][1] = acc[nt][2] = acc[nt][3] = 0.f; }
#pragma unroll
        for (int k0 = 0; k0 < 128; k0 += 8) {
            uint32_t a[4];
            a[0] = f2u(hid[(eg0 + g) * 132 + k0 + t4]);
            a[1] = f2u(hid[(eg0 + g + 8) * 132 + k0 + t4]);
            a[2] = f2u(hid[(eg0 + g) * 132 + k0 + t4 + 4]);
            a[3] = f2u(hid[(eg0 + g + 8) * 132 + k0 + t4 + 4]);
#pragma unroll
            for (int nt = 0; nt < 8; nt++) {
                int c = ng0 + nt * 8 + g;
                uint32_t b0 = f2u(W2s[wsw(k0 + t4, c)]);
                uint32_t b1v = f2u(W2s[wsw(k0 + t4 + 4, c)]);
                MMA8(acc[nt], a, b0, b1v);
            }
        }

        float s_a = 0.f, s_b = 0.f;
#pragma unroll
        for (int nt = 0; nt < 8; nt++) {
            int c0 = ng0 + nt * 8 + 2 * t4;
            float m0 = siluf(acc[nt][0] + b2_s[c0]);
            float m1 = siluf(acc[nt][1] + b2_s[c0 + 1]);
            float m2 = siluf(acc[nt][2] + b2_s[c0]);
            float m3 = siluf(acc[nt][3] + b2_s[c0 + 1]);
            acc[nt][0] = m0; acc[nt][1] = m1; acc[nt][2] = m2; acc[nt][3] = m3;
            s_a += m0 * at_s[c0] + m1 * at_s[c0 + 1];
            s_b += m2 * at_s[c0] + m3 * at_s[c0 + 1];
        }
        s_a += __shfl_xor_sync(0xffffffffu, s_a, 1);
        s_a += __shfl_xor_sync(0xffffffffu, s_a, 2);
        s_b += __shfl_xor_sync(0xffffffffu, s_b, 1);
        s_b += __shfl_xor_sync(0xffffffffu, s_b, 2);
        if (t4 == 0) {
            gp_s[(eg0 + g) * 2 + wn] = s_a;
            gp_s[(eg0 + g + 8) * 2 + wn] = s_b;
        }
        __syncthreads();

        {
            int ra = eg0 + g, rb = ra + 8;
            float gt_a = sigmf(gp_s[ra * 2] + gp_s[ra * 2 + 1] + attbv);
            float gt_b = sigmf(gp_s[rb * 2] + gp_s[rb * 2 + 1] + attbv);
            float* base_a = agg + (size_t)rows_s[ra] * 128 + ng0;
            float* base_b = agg + (size_t)rows_s[rb] * 128 + ng0;
            bool even = (t4 & 1) == 0;
#pragma unroll
            for (int nt = 0; nt < 8; nt++) {
                float send0 = even ? acc[nt][2] : acc[nt][0];
                float send1 = even ? acc[nt][3] : acc[nt][1];
                float rc0 = __shfl_xor_sync(0xffffffffu, send0, 1);
                float rc1 = __shfl_xor_sync(0xffffffffu, send1, 1);
                if (even) {
                    float* p = base_a + nt * 8 + 2 * t4;
                    asm volatile("red.global.add.v4.f32 [%0], {%1,%2,%3,%4};"
                                 :: "l"(p),
                                    "f"(acc[nt][0] * gt_a), "f"(acc[nt][1] * gt_a),
                                    "f"(rc0 * gt_a), "f"(rc1 * gt_a) : "memory");
                } else {
                    float* p = base_b + nt * 8 + 2 * (t4 - 1);
                    asm volatile("red.global.add.v4.f32 [%0], {%1,%2,%3,%4};"
                                 :: "l"(p),
                                    "f"(rc0 * gt_b), "f"(rc1 * gt_b),
                                    "f"(acc[nt][2] * gt_b), "f"(acc[nt][3] * gt_b) : "memory");
                }
            }
        }
    }
}

// ---------------- final head ----------------
__global__ void last2_kernel(const float* __restrict__ X, const float* __restrict__ w,
                             const float* __restrict__ b, float* __restrict__ out) {
    int gt = blockIdx.x * blockDim.x + threadIdx.x;
    int n = gt >> 5, lane = gt & 31;
    if (n >= N_NODES) return;
    float s = 0.f;
    for (int c = lane; c < 192; c += 32) s += X[(size_t)n * 192 + c] * w[c];
#pragma unroll
    for (int o = 16; o; o >>= 1) s += __shfl_down_sync(0xffffffffu, s, o);
    if (lane == 0) out[n] = sigmf(s + b[0]);
}

// ---------------- launch ----------------
extern "C" void kernel_launch(void* const* d_in, const int* in_sizes, int n_in,
                              void* d_out, int out_size) {
    const float* node_attrs = (const float*)d_in[0];
    const float* coords     = (const float*)d_in[1];
    const int*   ei         = (const int*)d_in[2];
    const float* ea         = (const float*)d_in[3];
    const float* emb_w  = (const float*)d_in[4];
    const float* emb_b  = (const float*)d_in[5];
    const float* edge_w1 = (const float*)d_in[6];
    const float* edge_b1 = (const float*)d_in[7];
    const float* edge_w2 = (const float*)d_in[8];
    const float* edge_b2 = (const float*)d_in[9];
    const float* att_w   = (const float*)d_in[10];
    const float* att_b   = (const float*)d_in[11];
    const float* node_w1 = (const float*)d_in[12];
    const float* node_b1 = (const float*)d_in[13];
    const float* node_w2 = (const float*)d_in[14];
    const float* node_b2 = (const float*)d_in[15];
    const float* dec_w1  = (const float*)d_in[16];
    const float* dec_b1  = (const float*)d_in[17];
    const float* dec_w2  = (const float*)d_in[18];
    const float* dec_b2  = (const float*)d_in[19];
    const float* ffnn_w1 = (const float*)d_in[20];
    const float* ffnn_b1 = (const float*)d_in[21];
    const float* ffnn_w2 = (const float*)d_in[22];
    const float* ffnn_b2 = (const float*)d_in[23];
    const float* last_w1 = (const float*)d_in[24];
    const float* last_b1 = (const float*)d_in[25];
    const float* last_w2 = (const float*)d_in[26];
    const float* last_b2 = (const float*)d_in[27];

    float *h, *PQ, *agg, *tmp, *esmin, *h0p, *esm1, *cat, *last, *radial;
    cudaGetSymbolAddress((void**)&h, g_h);
    cudaGetSymbolAddress((void**)&PQ, g_PQ);
    cudaGetSymbolAddress((void**)&agg, g_agg);
    cudaGetSymbolAddress((void**)&tmp, g_tmp);
    cudaGetSymbolAddress((void**)&esmin, g_esmin);
    cudaGetSymbolAddress((void**)&h0p, g_h0p);
    cudaGetSymbolAddress((void**)&esm1, g_esm1);
    cudaGetSymbolAddress((void**)&cat, g_cat);
    cudaGetSymbolAddress((void**)&last, g_last);
    cudaGetSymbolAddress((void**)&radial, g_radial);

    const int S64 = GEMM_SMEM_OF(64);
    const int S128 = GEMM_SMEM_OF(128);

    cudaFuncSetAttribute(edge_kernel, cudaFuncAttributeMaxDynamicSharedMemorySize, EDGE_SMEM);
    cudaFuncSetAttribute(gemm_tc<128, 2, false, true, 1, false, false>, cudaFuncAttributeMaxDynamicSharedMemorySize, S128);
    cudaFuncSetAttribute(gemm_tc<64, 0, false, true, 1, false, false>,  cudaFuncAttributeMaxDynamicSharedMemorySize, S64);
    cudaFuncSetAttribute(gemm_tc<64, 2, false, true, 1, false, false>,  cudaFuncAttributeMaxDynamicSharedMemorySize, S64);
    cudaFuncSetAttribute(gemm_tc<64, 0, false, false, 1, true, true>,   cudaFuncAttributeMaxDynamicSharedMemorySize, S64);
    cudaFuncSetAttribute(gemm_tc<64, 1, false, true, 3, false, false>,  cudaFuncAttributeMaxDynamicSharedMemorySize, S64);
    cudaFuncSetAttribute(gemm_tc<64, 0, true, true, 1, false, false>,   cudaFuncAttributeMaxDynamicSharedMemorySize, S64);
    cudaFuncSetAttribute(gemm_tc<64, 1, false, true, 1, false, false>,  cudaFuncAttributeMaxDynamicSharedMemorySize, S64);

    // Side stream + events (host handles only; created once, never destroyed).
    static cudaStream_t s_esm = nullptr;
    static cudaEvent_t ev0 = nullptr, ev_fork = nullptr, ev_rad = nullptr, ev_join = nullptr;
    if (!s_esm) {
        cudaStreamCreateWithFlags(&s_esm, cudaStreamNonBlocking);
        cudaEventCreateWithFlags(&ev0, cudaEventDisableTiming);
        cudaEventCreateWithFlags(&ev_fork, cudaEventDisableTiming);
        cudaEventCreateWithFlags(&ev_rad, cudaEventDisableTiming);
        cudaEventCreateWithFlags(&ev_join, cudaEventDisableTiming);
    }

    const int GBM = (N_NODES + 127) / 128;   // 391
    const int GB64 = (N_NODES + 63) / 64;    // 782
    const int EGB = (N_TILES + EDGE_TILES - 1) / EDGE_TILES;

    // ---- fork immediately: radial on side stream (inputs only) ----
    cudaEventRecord(ev0, 0);
    cudaStreamWaitEvent(s_esm, ev0, 0);
    radial_kernel<<<(N_EDGES + 255) / 256, 256, 0, s_esm>>>(coords, ei, radial);
    cudaEventRecord(ev_rad, s_esm);

    copy_inputs<<<N_NODES, 256>>>(node_attrs, esmin, h0p);

    // ---- ESM branch on side stream ----
    cudaEventRecord(ev_fork, 0);
    cudaStreamWaitEvent(s_esm, ev_fork, 0);
    gemm_tc<128, 2, false, true, 1, false, false><<<dim3(GBM, 2), 256, S128, s_esm>>>(
        esmin, nullptr, nullptr, F_ESM, 0, ffnn_w1, 256, 256, ffnn_b1, esm1, 256,
        N_NODES, F_ESM, F_ESM, 256, nullptr);
    gemm_tc<64, 2, false, true, 1, false, false><<<dim3(GB64, 1), 256, S64, s_esm>>>(
        esm1, nullptr, nullptr, 256, 0, ffnn_w2, 64, 64, ffnn_b2, cat + 128, 192,
        N_NODES, 256, 256, 64, nullptr);
    cudaEventRecord(ev_join, s_esm);

    // ---- main chain ----
    gemm_tc<64, 0, false, true, 1, false, false><<<dim3(GB64, 1), 256, S64>>>(
        h0p, nullptr, nullptr, H0P, 0, emb_w, 128, 128, emb_b, h, 128,
        N_NODES, H0P, F_STRUCT, 128, nullptr);

    cudaStreamWaitEvent(0, ev_rad, 0);   // edge layer 0 needs radial
    for (int i = 0; i < NLAYERS; i++) {
        const float* W1 = edge_w1 + (size_t)i * 258 * 128;
        const float* Wn = node_w1 + (size_t)i * NODE_IN * 128;
        // PQ = h @ [W1a | W1b]; blocks with y==0 also zero agg rows
        gemm_tc<64, 0, false, false, 1, true, true><<<dim3(GB64, 2), 256, S64>>>(
            h, nullptr, nullptr, 128, 0, W1, 128, 128, nullptr, PQ, 256,
            N_NODES, 128, 128, 256, agg);
        edge_kernel<<<EGB, 256, EDGE_SMEM>>>(PQ, radial, ea, ei,
                                             W1 + 256 * 128, W1 + 257 * 128,
                                             edge_b1 + (size_t)i * 128,
                                             edge_w2 + (size_t)i * 128 * 128,
                                             edge_b2 + (size_t)i * 128,
                                             att_w + (size_t)i * 128,
                                             att_b + i, agg);
        // tmp = silu([h|agg|h0] @ Wn + b1)
        gemm_tc<64, 1, false, true, 3, false, false><<<dim3(GB64, 1), 256, S64>>>(
            h, agg, h0p, 128, H0P, Wn, 128, 128, node_b1 + (size_t)i * 128,
            tmp, 128, N_NODES, 352, NODE_IN, 128, nullptr);
        gemm_tc<64, 0, true, true, 1, false, false><<<dim3(GB64, 1), 256, S64>>>(
            tmp, nullptr, nullptr, 128, 0, node_w2 + (size_t)i * 128 * 128, 128, 128,
            node_b2 + (size_t)i * 128, h, 128, N_NODES, 128, 128, 128, nullptr);
    }

    // decoder -> cat[:,0:128]
    gemm_tc<64, 1, false, true, 1, false, false><<<dim3(GB64, 1), 256, S64>>>(
        h, nullptr, nullptr, 128, 0, dec_w1, 128, 128, dec_b1, tmp, 128,
        N_NODES, 128, 128, 128, nullptr);
    gemm_tc<64, 0, false, true, 1, false, false><<<dim3(GB64, 1), 256, S64>>>(
        tmp, nullptr, nullptr, 128, 0, dec_w2, 128, 128, dec_b2, cat, 192,
        N_NODES, 128, 128, 128, nullptr);

    // ---- join + final head ----
    cudaStreamWaitEvent(0, ev_join, 0);
    gemm_tc<64, 1, false, true, 1, false, false><<<dim3(GB64, 2), 256, S64>>>(
        cat, nullptr, nullptr, 192, 0, last_w1, 192, 192, last_b1, last, 192,
        N_NODES, 192, 192, 192, nullptr);
    last2_kernel<<<(N_NODES * 32 + 255) / 256, 256>>>(last, last_w2, last_b2, (float*)d_out);
}

// round 15
// speedup vs baseline: 1.1037x; 1.1037x over previous
#include <cuda_runtime.h>
#include <math.h>
#include <stdint.h>

#define N_NODES 50000
#define N_EDGES 800000
#define H1 128
#define F_NODE 1363
#define F_STRUCT 83
#define F_ESM 1280
#define NODE_IN 339
#define H0P 96
#define NLAYERS 4

// ---------------- scratch ----------------
__device__ float g_h[N_NODES * H1];
__device__ float g_PQ[N_NODES * 256];
__device__ float g_agg[N_NODES * H1];
__device__ float g_tmp[N_NODES * H1];
__device__ float g_esmin[N_NODES * F_ESM];
__device__ float g_h0p[N_NODES * H0P];
__device__ float g_esm1[N_NODES * 256];
__device__ float g_cat[N_NODES * 192];
__device__ float g_last[N_NODES * 192];
__device__ float g_radial[N_EDGES];

__device__ __forceinline__ float siluf(float x) { return x / (1.f + __expf(-x)); }
__device__ __forceinline__ float sigmf(float x) { return 1.f / (1.f + __expf(-x)); }
__device__ __forceinline__ uint32_t f2u(float x) { return __float_as_uint(x); }

#define MMA8(d, a, b0, b1)                                                    \
    asm volatile(                                                             \
        "mma.sync.aligned.m16n8k8.row.col.f32.tf32.tf32.f32 "                 \
        "{%0,%1,%2,%3}, {%4,%5,%6,%7}, {%8,%9}, {%0,%1,%2,%3};"               \
        : "+f"(d[0]), "+f"(d[1]), "+f"(d[2]), "+f"(d[3])                      \
        : "r"(a[0]), "r"(a[1]), "r"(a[2]), "r"(a[3]), "r"(b0), "r"(b1))

__device__ __forceinline__ void cp_async16(uint32_t dst, const void* src, int sz) {
    asm volatile("cp.async.cg.shared.global [%0], [%1], 16, %2;"
                 :: "r"(dst), "l"(src), "r"(sz));
}
#define CP_COMMIT() asm volatile("cp.async.commit_group;")
template <int NW>
__device__ __forceinline__ void cp_wait() {
    asm volatile("cp.async.wait_group %0;" :: "n"(NW));
}

// ---------------- radial ----------------
__global__ void radial_kernel(const float* __restrict__ coords,
                              const int* __restrict__ ei,
                              float* __restrict__ radial) {
    int e = blockIdx.x * blockDim.x + threadIdx.x;
    if (e >= N_EDGES) return;
    int r = ei[e], c = ei[N_EDGES + e];
    float dx = coords[r * 3 + 0] - coords[c * 3 + 0];
    float dy = coords[r * 3 + 1] - coords[c * 3 + 1];
    float dz = coords[r * 3 + 2] - coords[c * 3 + 2];
    radial[e] = dx * dx + dy * dy + dz * dz;
}

// ---------------- copy inputs to aligned/padded buffers ----------------
__global__ void copy_inputs(const float* __restrict__ na,
                            float* __restrict__ esmd, float* __restrict__ h0p) {
    int n = blockIdx.x, t = threadIdx.x;
    const float* src = na + (size_t)n * F_NODE;
#pragma unroll
    for (int c = t; c < F_ESM; c += 256) esmd[(size_t)n * F_ESM + c] = src[F_STRUCT + c];
    if (t < H0P) h0p[(size_t)n * H0P + t] = (t < F_STRUCT) ? src[t] : 0.f;
}

// ---------------- shared tile constants ----------------
#define BKT 32
#define AS_STRIDE 36
#define WS_STRIDE 136
#define WS_SZ (BKT * WS_STRIDE)
#define GEMM_SMEM_OF(BM, STG) (((BM) * AS_STRIDE + WS_SZ) * (STG) * 4)

// ---------------- async pipelined tf32 GEMM, templated block-M & stages ----
// 8 warps. BM=128: 4m x 2n (warp 32x64, NT=8). BM=64: 2m x 4n (warp 32x32, NT=4).
// STG=2: 53KB smem -> 4 blocks/SM (small-K). STG=3: deeper pipeline (large-K).
template <int BM, int STG, int ACT, bool RESID, bool BIAS, int NX, bool WSPLIT, bool ZAGG>
__global__ __launch_bounds__(256) void gemm_tc(
        const float* __restrict__ X, const float* __restrict__ X2,
        const float* __restrict__ X3, int ldx, int ldx3,
        const float* __restrict__ W, int ldw, int COw,
        const float* __restrict__ B,
        float* __restrict__ Y, int ldy,
        int M, int K, int KW, int CO,
        float* __restrict__ aggz) {
    constexpr int WM = BM / 32;          // warps along m (4 or 2)
    constexpr int NT = 2 * WM;           // 8-col groups per warp (8 or 4)
    constexpr int AS_SZ = BM * AS_STRIDE;
    constexpr int STAGE_SZ = AS_SZ + WS_SZ;

    extern __shared__ float smn[];
    uint32_t sm_u = (uint32_t)__cvta_generic_to_shared(smn);

    int t = threadIdx.x;
    int warp = t >> 5, lane = t & 31;
    int g = lane >> 2, t4 = lane & 3;
    int wm = warp % WM, wn = warp / WM;
    int m0 = blockIdx.x * BM, cb = blockIdx.y * 128;

    const float* Wbase = WSPLIT ? (W + (size_t)blockIdx.y * 128 * 128) : W;
    int cw = WSPLIT ? 0 : cb;

    float acc[2][NT][4];
#pragma unroll
    for (int i = 0; i < 2; i++)
#pragma unroll
        for (int nt = 0; nt < NT; nt++)
            acc[i][nt][0] = acc[i][nt][1] = acc[i][nt][2] = acc[i][nt][3] = 0.f;

    auto loadA = [&](int buf, int k0) {
        const float* Xs = X; int kb = k0, ld = ldx;
        if (NX >= 3 && k0 >= 256)      { Xs = X3; kb = k0 - 256; ld = ldx3; }
        else if (NX >= 2 && k0 >= 128) { Xs = X2; kb = k0 - 128; }
#pragma unroll
        for (int i = 0; i < BM / 32; i++) {
            int idx = t + i * 256;
            int r = idx >> 3, c4 = (idx & 7) * 4;
            uint32_t dst = sm_u + (buf * STAGE_SZ + r * AS_STRIDE + c4) * 4;
            const float* src = Xs + (size_t)(m0 + r) * ld + kb + c4;
            cp_async16(dst, src, (m0 + r < M) ? 16 : 0);
        }
    };
    auto loadW = [&](int buf, int k0) {
#pragma unroll
        for (int i = 0; i < 4; i++) {
            int idx = t + i * 256;
            int kk = idx >> 5, c4 = (idx & 31) * 4;
            uint32_t dst = sm_u + (buf * STAGE_SZ + AS_SZ + kk * WS_STRIDE + c4) * 4;
            const float* src = Wbase + (size_t)(k0 + kk) * ldw + cw + c4;
            cp_async16(dst, src, (k0 + kk < KW && cw + c4 < COw) ? 16 : 0);
        }
    };

    int nk = K / BKT;
    loadA(0, 0); loadW(0, 0); CP_COMMIT();
    if (nk > 1) { loadA(1 % STG, BKT); loadW(1 % STG, BKT); }
    CP_COMMIT();

    for (int ki = 0; ki < nk; ki++) {
        int buf = ki % STG;
        cp_wait<1>();
        __syncthreads();
        const float* A = smn + buf * STAGE_SZ;
        const float* Wb = A + AS_SZ;
#pragma unroll
        for (int ks = 0; ks < BKT; ks += 8) {
            uint32_t a[2][4];
#pragma unroll
            for (int i = 0; i < 2; i++) {
                int r = wm * 32 + i * 16 + g;
                a[i][0] = f2u(A[r * AS_STRIDE + ks + t4]);
                a[i][1] = f2u(A[(r + 8) * AS_STRIDE + ks + t4]);
                a[i][2] = f2u(A[r * AS_STRIDE + ks + t4 + 4]);
                a[i][3] = f2u(A[(r + 8) * AS_STRIDE + ks + t4 + 4]);
            }
#pragma unroll
            for (int nt = 0; nt < NT; nt++) {
                int c = wn * (NT * 8) + nt * 8 + g;
                uint32_t b0 = f2u(Wb[(ks + t4) * WS_STRIDE + c]);
                uint32_t b1 = f2u(Wb[(ks + t4 + 4) * WS_STRIDE + c]);
                MMA8(acc[0][nt], a[0], b0, b1);
                MMA8(acc[1][nt], a[1], b0, b1);
            }
        }
        __syncthreads();
        if (ki + 2 < nk) {
            int nbuf = (ki + 2) % STG;   // consumer at ki+2 reads this buffer
            loadA(nbuf, (ki + 2) * BKT);
            loadW(nbuf, (ki + 2) * BKT);
        }
        CP_COMMIT();
    }

    // epilogue
#pragma unroll
    for (int i = 0; i < 2; i++) {
        int rA = m0 + wm * 32 + i * 16 + g;
        int rB = rA + 8;
#pragma unroll
        for (int nt = 0; nt < NT; nt++) {
            int c = cb + wn * (NT * 8) + nt * 8 + 2 * t4;
            if (c >= CO) continue;
            float b0v = 0.f, b1v = 0.f;
            if (BIAS) { b0v = B[c]; b1v = B[c + 1]; }
#pragma unroll
            for (int h2 = 0; h2 < 2; h2++) {
                int m = h2 ? rB : rA;
                if (m >= M) continue;
                float x0 = acc[i][nt][h2 * 2 + 0] + b0v;
                float x1 = acc[i][nt][h2 * 2 + 1] + b1v;
                if (ACT == 1) { x0 = siluf(x0); x1 = siluf(x1); }
                if (ACT == 2) { x0 = fmaxf(x0, 0.f); x1 = fmaxf(x1, 0.f); }
                float* yp = Y + (size_t)m * ldy + c;
                if (RESID) { float2 o = *(const float2*)yp; x0 += o.x; x1 += o.y; }
                float2 o; o.x = x0; o.y = x1;
                *(float2*)yp = o;
            }
        }
    }

    // optional: zero agg rows for this m-block (replaces cudaMemsetAsync)
    if (ZAGG && blockIdx.y == 0) {
        float4 z = {0.f, 0.f, 0.f, 0.f};
#pragma unroll
        for (int i = 0; i < BM / 8; i++) {
            int idx = t + i * 256;
            int r = idx >> 5, c4 = (idx & 31) * 4;
            if (m0 + r < M) *(float4*)(aggz + (size_t)(m0 + r) * 128 + c4) = z;
        }
    }
}

// ---------------- fused edge layer: register epilogue + register scatter ----
#define TILE_E 64
#define EDGE_TILES 4
#define N_TILES (N_EDGES / TILE_E)        // 12500
#define OFF_W2S   0                        // [128][136]
#define OFF_HID   (128*136)                // [64][132]
#define OFF_WR    (OFF_HID + 64*132)
#define OFF_WE    (OFF_WR + 128)
#define OFF_B1    (OFF_WE + 128)
#define OFF_ATT   (OFF_B1 + 128)
#define OFF_B2    (OFF_ATT + 128)
#define OFF_RAD   (OFF_B2 + 128)
#define OFF_EA    (OFF_RAD + 64)
#define OFF_GPART (OFF_EA + 64)            // [64][2] gate partials
#define OFF_ROWS  (OFF_GPART + 128)
#define OFF_COLS  (OFF_ROWS + 64)
#define EDGE_SMEM ((OFF_COLS + 64) * 4)

__global__ __launch_bounds__(256) void edge_kernel(
        const float* __restrict__ PQ,
        const float* __restrict__ radial, const float* __restrict__ ea,
        const int* __restrict__ ei,
        const float* __restrict__ wr, const float* __restrict__ we,
        const float* __restrict__ b1,
        const float* __restrict__ W2, const float* __restrict__ B2,
        const float* __restrict__ attw, const float* __restrict__ attb,
        float* __restrict__ agg) {
    extern __shared__ float sm[];
    float* W2s  = sm + OFF_W2S;
    float* hid  = sm + OFF_HID;
    float* wr_s = sm + OFF_WR;
    float* we_s = sm + OFF_WE;
    float* b1_s = sm + OFF_B1;
    float* at_s = sm + OFF_ATT;
    float* b2_s = sm + OFF_B2;
    float* rd_s = sm + OFF_RAD;
    float* ea_s = sm + OFF_EA;
    float* gp_s = sm + OFF_GPART;
    int* rows_s = (int*)(sm + OFF_ROWS);
    int* cols_s = (int*)(sm + OFF_COLS);

    int t = threadIdx.x;
    int w = t >> 5, lane = t & 31;
    int g = lane >> 2, t4 = lane & 3;
    int eg0 = (w & 3) * 16, ng0 = (w >> 2) * 64;
    int wn = w >> 2;
    float attbv = attb[0];

    for (int idx = t; idx < 5 * 128; idx += 256) {
        int a = idx >> 7, c = idx & 127;
        float v;
        if (a == 0) v = wr[c];
        else if (a == 1) v = we[c];
        else if (a == 2) v = b1[c];
        else if (a == 3) v = attw[c];
        else v = B2[c];
        sm[OFF_WR + a * 128 + c] = v;
    }
    for (int idx = t; idx < 128 * 32; idx += 256) {
        int kk = idx >> 5, c4 = (idx & 31) * 4;
        *(float4*)&W2s[kk * 136 + c4] = *(const float4*)(W2 + (size_t)kk * 128 + c4);
    }

    for (int tt = 0; tt < EDGE_TILES; tt++) {
        int tile = blockIdx.x * EDGE_TILES + tt;
        if (tile >= N_TILES) break;
        int e0 = tile * TILE_E;

        __syncthreads();
        if (t < TILE_E) {
            rows_s[t] = ei[e0 + t];
            rd_s[t] = radial[e0 + t];
            ea_s[t] = ea[e0 + t];
        } else if (t < 2 * TILE_E) {
            cols_s[t - TILE_E] = ei[N_EDGES + e0 + (t - TILE_E)];
        }
        __syncthreads();

#pragma unroll
        for (int i = 0; i < 8; i++) {
            int idx = t + i * 256;
            int e = idx >> 5, c4 = (idx & 31) * 4;
            float4 p = *(const float4*)(PQ + (size_t)rows_s[e] * 256 + c4);
            float4 q = *(const float4*)(PQ + (size_t)cols_s[e] * 256 + 128 + c4);
            float rd = rd_s[e], eav = ea_s[e];
            float4 o;
            o.x = siluf(p.x + q.x + rd * wr_s[c4 + 0] + eav * we_s[c4 + 0] + b1_s[c4 + 0]);
            o.y = siluf(p.y + q.y + rd * wr_s[c4 + 1] + eav * we_s[c4 + 1] + b1_s[c4 + 1]);
            o.z = siluf(p.z + q.z + rd * wr_s[c4 + 2] + eav * we_s[c4 + 2] + b1_s[c4 + 2]);
            o.w = siluf(p.w + q.w + rd * wr_s[c4 + 3] + eav * we_s[c4 + 3] + b1_s[c4 + 3]);
            *(float4*)&hid[e * 132 + c4] = o;
        }
        __syncthreads();

        float acc[8][4];
#pragma unroll
        for (int nt = 0; nt < 8; nt++) { acc[nt][0] = acc[nt][1] = acc[nt][2] = acc[nt][3] = 0.f; }
#pragma unroll
        for (int k0 = 0; k0 < 128; k0 += 8) {
            uint32_t a[4];
            a[0] = f2u(hid[(eg0 + g) * 132 + k0 + t4]);
            a[1] = f2u(hid[(eg0 + g + 8) * 132 + k0 + t4]);
            a[2] = f2u(hid[(eg0 + g) * 132 + k0 + t4 + 4]);
            a[3] = f2u(hid[(eg0 + g + 8) * 132 + k0 + t4 + 4]);
#pragma unroll
            for (int nt = 0; nt < 8; nt++) {
                uint32_t b0 = f2u(W2s[(k0 + t4) * 136 + ng0 + nt * 8 + g]);
                uint32_t b1v = f2u(W2s[(k0 + t4 + 4) * 136 + ng0 + nt * 8 + g]);
                MMA8(acc[nt], a, b0, b1v);
            }
        }

        float s_a = 0.f, s_b = 0.f;
#pragma unroll
        for (int nt = 0; nt < 8; nt++) {
            int c0 = ng0 + nt * 8 + 2 * t4;
            float m0 = siluf(acc[nt][0] + b2_s[c0]);
            float m1 = siluf(acc[nt][1] + b2_s[c0 + 1]);
            float m2 = siluf(acc[nt][2] + b2_s[c0]);
            float m3 = siluf(acc[nt][3] + b2_s[c0 + 1]);
            acc[nt][0] = m0; acc[nt][1] = m1; acc[nt][2] = m2; acc[nt][3] = m3;
            s_a += m0 * at_s[c0] + m1 * at_s[c0 + 1];
            s_b += m2 * at_s[c0] + m3 * at_s[c0 + 1];
        }
        s_a += __shfl_xor_sync(0xffffffffu, s_a, 1);
        s_a += __shfl_xor_sync(0xffffffffu, s_a, 2);
        s_b += __shfl_xor_sync(0xffffffffu, s_b, 1);
        s_b += __shfl_xor_sync(0xffffffffu, s_b, 2);
        if (t4 == 0) {
            gp_s[(eg0 + g) * 2 + wn] = s_a;
            gp_s[(eg0 + g + 8) * 2 + wn] = s_b;
        }
        __syncthreads();

        {
            int ra = eg0 + g, rb = ra + 8;
            float gt_a = sigmf(gp_s[ra * 2] + gp_s[ra * 2 + 1] + attbv);
            float gt_b = sigmf(gp_s[rb * 2] + gp_s[rb * 2 + 1] + attbv);
            float* base_a = agg + (size_t)rows_s[ra] * 128 + ng0;
            float* base_b = agg + (size_t)rows_s[rb] * 128 + ng0;
            bool even = (t4 & 1) == 0;
#pragma unroll
            for (int nt = 0; nt < 8; nt++) {
                float send0 = even ? acc[nt][2] : acc[nt][0];
                float send1 = even ? acc[nt][3] : acc[nt][1];
                float rc0 = __shfl_xor_sync(0xffffffffu, send0, 1);
                float rc1 = __shfl_xor_sync(0xffffffffu, send1, 1);
                if (even) {
                    float* p = base_a + nt * 8 + 2 * t4;
                    asm volatile("red.global.add.v4.f32 [%0], {%1,%2,%3,%4};"
                                 :: "l"(p),
                                    "f"(acc[nt][0] * gt_a), "f"(acc[nt][1] * gt_a),
                                    "f"(rc0 * gt_a), "f"(rc1 * gt_a) : "memory");
                } else {
                    float* p = base_b + nt * 8 + 2 * (t4 - 1);
                    asm volatile("red.global.add.v4.f32 [%0], {%1,%2,%3,%4};"
                                 :: "l"(p),
                                    "f"(rc0 * gt_b), "f"(rc1 * gt_b),
                                    "f"(acc[nt][2] * gt_b), "f"(acc[nt][3] * gt_b) : "memory");
                }
            }
        }
    }
}

// ---------------- final head ----------------
__global__ void last2_kernel(const float* __restrict__ X, const float* __restrict__ w,
                             const float* __restrict__ b, float* __restrict__ out) {
    int gt = blockIdx.x * blockDim.x + threadIdx.x;
    int n = gt >> 5, lane = gt & 31;
    if (n >= N_NODES) return;
    float s = 0.f;
    for (int c = lane; c < 192; c += 32) s += X[(size_t)n * 192 + c] * w[c];
#pragma unroll
    for (int o = 16; o; o >>= 1) s += __shfl_down_sync(0xffffffffu, s, o);
    if (lane == 0) out[n] = sigmf(s + b[0]);
}

// ---------------- launch ----------------
extern "C" void kernel_launch(void* const* d_in, const int* in_sizes, int n_in,
                              void* d_out, int out_size) {
    const float* node_attrs = (const float*)d_in[0];
    const float* coords     = (const float*)d_in[1];
    const int*   ei         = (const int*)d_in[2];
    const float* ea         = (const float*)d_in[3];
    const float* emb_w  = (const float*)d_in[4];
    const float* emb_b  = (const float*)d_in[5];
    const float* edge_w1 = (const float*)d_in[6];
    const float* edge_b1 = (const float*)d_in[7];
    const float* edge_w2 = (const float*)d_in[8];
    const float* edge_b2 = (const float*)d_in[9];
    const float* att_w   = (const float*)d_in[10];
    const float* att_b   = (const float*)d_in[11];
    const float* node_w1 = (const float*)d_in[12];
    const float* node_b1 = (const float*)d_in[13];
    const float* node_w2 = (const float*)d_in[14];
    const float* node_b2 = (const float*)d_in[15];
    const float* dec_w1  = (const float*)d_in[16];
    const float* dec_b1  = (const float*)d_in[17];
    const float* dec_w2  = (const float*)d_in[18];
    const float* dec_b2  = (const float*)d_in[19];
    const float* ffnn_w1 = (const float*)d_in[20];
    const float* ffnn_b1 = (const float*)d_in[21];
    const float* ffnn_w2 = (const float*)d_in[22];
    const float* ffnn_b2 = (const float*)d_in[23];
    const float* last_w1 = (const float*)d_in[24];
    const float* last_b1 = (const float*)d_in[25];
    const float* last_w2 = (const float*)d_in[26];
    const float* last_b2 = (const float*)d_in[27];

    float *h, *PQ, *agg, *tmp, *esmin, *h0p, *esm1, *cat, *last, *radial;
    cudaGetSymbolAddress((void**)&h, g_h);
    cudaGetSymbolAddress((void**)&PQ, g_PQ);
    cudaGetSymbolAddress((void**)&agg, g_agg);
    cudaGetSymbolAddress((void**)&tmp, g_tmp);
    cudaGetSymbolAddress((void**)&esmin, g_esmin);
    cudaGetSymbolAddress((void**)&h0p, g_h0p);
    cudaGetSymbolAddress((void**)&esm1, g_esm1);
    cudaGetSymbolAddress((void**)&cat, g_cat);
    cudaGetSymbolAddress((void**)&last, g_last);
    cudaGetSymbolAddress((void**)&radial, g_radial);

    const int S64 = GEMM_SMEM_OF(64, 2);     // ~53 KB -> 4 blocks/SM
    const int S128 = GEMM_SMEM_OF(128, 3);   // ESM1 deep pipeline

    cudaFuncSetAttribute(edge_kernel, cudaFuncAttributeMaxDynamicSharedMemorySize, EDGE_SMEM);
    cudaFuncSetAttribute(gemm_tc<128, 3, 2, false, true, 1, false, false>, cudaFuncAttributeMaxDynamicSharedMemorySize, S128);
    cudaFuncSetAttribute(gemm_tc<64, 2, 0, false, true, 1, false, false>,  cudaFuncAttributeMaxDynamicSharedMemorySize, S64);
    cudaFuncSetAttribute(gemm_tc<64, 2, 2, false, true, 1, false, false>,  cudaFuncAttributeMaxDynamicSharedMemorySize, S64);
    cudaFuncSetAttribute(gemm_tc<64, 2, 0, false, false, 1, true, true>,   cudaFuncAttributeMaxDynamicSharedMemorySize, S64);
    cudaFuncSetAttribute(gemm_tc<64, 2, 1, false, true, 3, false, false>,  cudaFuncAttributeMaxDynamicSharedMemorySize, S64);
    cudaFuncSetAttribute(gemm_tc<64, 2, 0, true, true, 1, false, false>,   cudaFuncAttributeMaxDynamicSharedMemorySize, S64);
    cudaFuncSetAttribute(gemm_tc<64, 2, 1, false, true, 1, false, false>,  cudaFuncAttributeMaxDynamicSharedMemorySize, S64);

    // Side stream + events (host handles only; created once, never destroyed).
    static cudaStream_t s_esm = nullptr;
    static cudaEvent_t ev0 = nullptr, ev_fork = nullptr, ev_rad = nullptr, ev_join = nullptr;
    if (!s_esm) {
        cudaStreamCreateWithFlags(&s_esm, cudaStreamNonBlocking);
        cudaEventCreateWithFlags(&ev0, cudaEventDisableTiming);
        cudaEventCreateWithFlags(&ev_fork, cudaEventDisableTiming);
        cudaEventCreateWithFlags(&ev_rad, cudaEventDisableTiming);
        cudaEventCreateWithFlags(&ev_join, cudaEventDisableTiming);
    }

    const int GBM = (N_NODES + 127) / 128;   // 391
    const int GB64 = (N_NODES + 63) / 64;    // 782
    const int EGB = (N_TILES + EDGE_TILES - 1) / EDGE_TILES;

    // ---- fork immediately: radial on side stream (inputs only) ----
    cudaEventRecord(ev0, 0);
    cudaStreamWaitEvent(s_esm, ev0, 0);
    radial_kernel<<<(N_EDGES + 255) / 256, 256, 0, s_esm>>>(coords, ei, radial);
    cudaEventRecord(ev_rad, s_esm);

    copy_inputs<<<N_NODES, 256>>>(node_attrs, esmin, h0p);

    // ---- ESM branch on side stream ----
    cudaEventRecord(ev_fork, 0);
    cudaStreamWaitEvent(s_esm, ev_fork, 0);
    gemm_tc<128, 3, 2, false, true, 1, false, false><<<dim3(GBM, 2), 256, S128, s_esm>>>(
        esmin, nullptr, nullptr, F_ESM, 0, ffnn_w1, 256, 256, ffnn_b1, esm1, 256,
        N_NODES, F_ESM, F_ESM, 256, nullptr);
    gemm_tc<64, 2, 2, false, true, 1, false, false><<<dim3(GB64, 1), 256, S64, s_esm>>>(
        esm1, nullptr, nullptr, 256, 0, ffnn_w2, 64, 64, ffnn_b2, cat + 128, 192,
        N_NODES, 256, 256, 64, nullptr);
    cudaEventRecord(ev_join, s_esm);

    // ---- main chain ----
    gemm_tc<64, 2, 0, false, true, 1, false, false><<<dim3(GB64, 1), 256, S64>>>(
        h0p, nullptr, nullptr, H0P, 0, emb_w, 128, 128, emb_b, h, 128,
        N_NODES, H0P, F_STRUCT, 128, nullptr);

    cudaStreamWaitEvent(0, ev_rad, 0);   // edge layer 0 needs radial
    for (int i = 0; i < NLAYERS; i++) {
        const float* W1 = edge_w1 + (size_t)i * 258 * 128;
        const float* Wn = node_w1 + (size_t)i * NODE_IN * 128;
        // PQ = h @ [W1a | W1b]; blocks with y==0 also zero agg rows
        gemm_tc<64, 2, 0, false, false, 1, true, true><<<dim3(GB64, 2), 256, S64>>>(
            h, nullptr, nullptr, 128, 0, W1, 128, 128, nullptr, PQ, 256,
            N_NODES, 128, 128, 256, agg);
        edge_kernel<<<EGB, 256, EDGE_SMEM>>>(PQ, radial, ea, ei,
                                             W1 + 256 * 128, W1 + 257 * 128,
                                             edge_b1 + (size_t)i * 128,
                                             edge_w2 + (size_t)i * 128 * 128,
                                             edge_b2 + (size_t)i * 128,
                                             att_w + (size_t)i * 128,
                                             att_b + i, agg);
        // tmp = silu([h|agg|h0] @ Wn + b1)
        gemm_tc<64, 2, 1, false, true, 3, false, false><<<dim3(GB64, 1), 256, S64>>>(
            h, agg, h0p, 128, H0P, Wn, 128, 128, node_b1 + (size_t)i * 128,
            tmp, 128, N_NODES, 352, NODE_IN, 128, nullptr);
        gemm_tc<64, 2, 0, true, true, 1, false, false><<<dim3(GB64, 1), 256, S64>>>(
            tmp, nullptr, nullptr, 128, 0, node_w2 + (size_t)i * 128 * 128, 128, 128,
            node_b2 + (size_t)i * 128, h, 128, N_NODES, 128, 128, 128, nullptr);
    }

    // decoder -> cat[:,0:128]
    gemm_tc<64, 2, 1, false, true, 1, false, false><<<dim3(GB64, 1), 256, S64>>>(
        h, nullptr, nullptr, 128, 0, dec_w1, 128, 128, dec_b1, tmp, 128,
        N_NODES, 128, 128, 128, nullptr);
    gemm_tc<64, 2, 0, false, true, 1, false, false><<<dim3(GB64, 1), 256, S64>>>(
        tmp, nullptr, nullptr, 128, 0, dec_w2, 128, 128, dec_b2, cat, 192,
        N_NODES, 128, 128, 128, nullptr);

    // ---- join + final head ----
    cudaStreamWaitEvent(0, ev_join, 0);
    gemm_tc<64, 2, 1, false, true, 1, false, false><<<dim3(GB64, 2), 256, S64>>>(
        cat, nullptr, nullptr, 192, 0, last_w1, 192, 192, last_b1, last, 192,
        N_NODES, 192, 192, 192, nullptr);
    last2_kernel<<<(N_NODES * 32 + 255) / 256, 256>>>(last, last_w2, last_b2, (float*)d_out);
}

// round 16
// speedup vs baseline: 1.1718x; 1.0618x over previous
#include <cuda_runtime.h>
#include <cuda_bf16.h>
#include <math.h>
#include <stdint.h>

#define N_NODES 50000
#define N_EDGES 800000
#define H1 128
#define F_NODE 1363
#define F_STRUCT 83
#define F_ESM 1280
#define NODE_IN 339
#define H0P 96
#define NLAYERS 4

// ---------------- scratch ----------------
__device__ float g_h[N_NODES * H1];
__device__ __nv_bfloat16 g_PQb[N_NODES * 256];
__device__ float g_agg[N_NODES * H1];
__device__ float g_tmp[N_NODES * H1];
__device__ float g_esmin[N_NODES * F_ESM];
__device__ float g_h0p[N_NODES * H0P];
__device__ float g_esm1[N_NODES * 256];
__device__ float g_cat[N_NODES * 192];
__device__ float g_last[N_NODES * 192];
__device__ float g_radial[N_EDGES];

__device__ __forceinline__ float siluf(float x) { return x / (1.f + __expf(-x)); }
__device__ __forceinline__ float sigmf(float x) { return 1.f / (1.f + __expf(-x)); }
__device__ __forceinline__ uint32_t f2u(float x) { return __float_as_uint(x); }

#define MMA8(d, a, b0, b1)                                                    \
    asm volatile(                                                             \
        "mma.sync.aligned.m16n8k8.row.col.f32.tf32.tf32.f32 "                 \
        "{%0,%1,%2,%3}, {%4,%5,%6,%7}, {%8,%9}, {%0,%1,%2,%3};"               \
        : "+f"(d[0]), "+f"(d[1]), "+f"(d[2]), "+f"(d[3])                      \
        : "r"(a[0]), "r"(a[1]), "r"(a[2]), "r"(a[3]), "r"(b0), "r"(b1))

__device__ __forceinline__ void cp_async16(uint32_t dst, const void* src, int sz) {
    asm volatile("cp.async.cg.shared.global [%0], [%1], 16, %2;"
                 :: "r"(dst), "l"(src), "r"(sz));
}
#define CP_COMMIT() asm volatile("cp.async.commit_group;")
template <int NW>
__device__ __forceinline__ void cp_wait() {
    asm volatile("cp.async.wait_group %0;" :: "n"(NW));
}

// ---------------- radial ----------------
__global__ void radial_kernel(const float* __restrict__ coords,
                              const int* __restrict__ ei,
                              float* __restrict__ radial) {
    int e = blockIdx.x * blockDim.x + threadIdx.x;
    if (e >= N_EDGES) return;
    int r = ei[e], c = ei[N_EDGES + e];
    float dx = coords[r * 3 + 0] - coords[c * 3 + 0];
    float dy = coords[r * 3 + 1] - coords[c * 3 + 1];
    float dz = coords[r * 3 + 2] - coords[c * 3 + 2];
    radial[e] = dx * dx + dy * dy + dz * dz;
}

// ---------------- input staging (split: h0p on critical path, esm off) -----
__global__ void copy_h0p(const float* __restrict__ na, float* __restrict__ h0p) {
    int idx = blockIdx.x * blockDim.x + threadIdx.x;
    if (idx >= N_NODES * H0P) return;
    int n = idx / H0P, c = idx % H0P;
    h0p[idx] = (c < F_STRUCT) ? na[(size_t)n * F_NODE + c] : 0.f;
}
__global__ void copy_esm(const float* __restrict__ na, float* __restrict__ esmd) {
    int n = blockIdx.x, t = threadIdx.x;
    const float* src = na + (size_t)n * F_NODE + F_STRUCT;
#pragma unroll
    for (int c = t; c < F_ESM; c += 256) esmd[(size_t)n * F_ESM + c] = src[c];
}

// ---------------- shared tile constants ----------------
#define BKT 32
#define AS_STRIDE 36
#define WS_STRIDE 136
#define WS_SZ (BKT * WS_STRIDE)
#define GEMM_SMEM_OF(BM, STG) (((BM) * AS_STRIDE + WS_SZ) * (STG) * 4)

// ---------------- async pipelined tf32 GEMM ----------------
// 8 warps. BM=128: 4m x 2n (NT=8). BM=64: 2m x 4n (NT=4).
// OBF16: store output as bf16 (RN), ldy in elements.
template <int BM, int STG, int ACT, bool RESID, bool BIAS, int NX, bool WSPLIT,
          bool ZAGG, bool OBF16>
__global__ __launch_bounds__(256) void gemm_tc(
        const float* __restrict__ X, const float* __restrict__ X2,
        const float* __restrict__ X3, int ldx, int ldx3,
        const float* __restrict__ W, int ldw, int COw,
        const float* __restrict__ B,
        float* __restrict__ Y, int ldy,
        int M, int K, int KW, int CO,
        float* __restrict__ aggz) {
    constexpr int WM = BM / 32;
    constexpr int NT = 2 * WM;
    constexpr int AS_SZ = BM * AS_STRIDE;
    constexpr int STAGE_SZ = AS_SZ + WS_SZ;

    extern __shared__ float smn[];
    uint32_t sm_u = (uint32_t)__cvta_generic_to_shared(smn);

    int t = threadIdx.x;
    int warp = t >> 5, lane = t & 31;
    int g = lane >> 2, t4 = lane & 3;
    int wm = warp % WM, wn = warp / WM;
    int m0 = blockIdx.x * BM, cb = blockIdx.y * 128;

    const float* Wbase = WSPLIT ? (W + (size_t)blockIdx.y * 128 * 128) : W;
    int cw = WSPLIT ? 0 : cb;

    float acc[2][NT][4];
#pragma unroll
    for (int i = 0; i < 2; i++)
#pragma unroll
        for (int nt = 0; nt < NT; nt++)
            acc[i][nt][0] = acc[i][nt][1] = acc[i][nt][2] = acc[i][nt][3] = 0.f;

    auto loadA = [&](int buf, int k0) {
        const float* Xs = X; int kb = k0, ld = ldx;
        if (NX >= 3 && k0 >= 256)      { Xs = X3; kb = k0 - 256; ld = ldx3; }
        else if (NX >= 2 && k0 >= 128) { Xs = X2; kb = k0 - 128; }
#pragma unroll
        for (int i = 0; i < BM / 32; i++) {
            int idx = t + i * 256;
            int r = idx >> 3, c4 = (idx & 7) * 4;
            uint32_t dst = sm_u + (buf * STAGE_SZ + r * AS_STRIDE + c4) * 4;
            const float* src = Xs + (size_t)(m0 + r) * ld + kb + c4;
            cp_async16(dst, src, (m0 + r < M) ? 16 : 0);
        }
    };
    auto loadW = [&](int buf, int k0) {
#pragma unroll
        for (int i = 0; i < 4; i++) {
            int idx = t + i * 256;
            int kk = idx >> 5, c4 = (idx & 31) * 4;
            uint32_t dst = sm_u + (buf * STAGE_SZ + AS_SZ + kk * WS_STRIDE + c4) * 4;
            const float* src = Wbase + (size_t)(k0 + kk) * ldw + cw + c4;
            cp_async16(dst, src, (k0 + kk < KW && cw + c4 < COw) ? 16 : 0);
        }
    };

    int nk = K / BKT;
    loadA(0, 0); loadW(0, 0); CP_COMMIT();
    if (nk > 1) { loadA(1 % STG, BKT); loadW(1 % STG, BKT); }
    CP_COMMIT();

    for (int ki = 0; ki < nk; ki++) {
        int buf = ki % STG;
        cp_wait<1>();
        __syncthreads();
        const float* A = smn + buf * STAGE_SZ;
        const float* Wb = A + AS_SZ;
#pragma unroll
        for (int ks = 0; ks < BKT; ks += 8) {
            uint32_t a[2][4];
#pragma unroll
            for (int i = 0; i < 2; i++) {
                int r = wm * 32 + i * 16 + g;
                a[i][0] = f2u(A[r * AS_STRIDE + ks + t4]);
                a[i][1] = f2u(A[(r + 8) * AS_STRIDE + ks + t4]);
                a[i][2] = f2u(A[r * AS_STRIDE + ks + t4 + 4]);
                a[i][3] = f2u(A[(r + 8) * AS_STRIDE + ks + t4 + 4]);
            }
#pragma unroll
            for (int nt = 0; nt < NT; nt++) {
                int c = wn * (NT * 8) + nt * 8 + g;
                uint32_t b0 = f2u(Wb[(ks + t4) * WS_STRIDE + c]);
                uint32_t b1 = f2u(Wb[(ks + t4 + 4) * WS_STRIDE + c]);
                MMA8(acc[0][nt], a[0], b0, b1);
                MMA8(acc[1][nt], a[1], b0, b1);
            }
        }
        __syncthreads();
        if (ki + 2 < nk) {
            int nbuf = (ki + 2) % STG;
            loadA(nbuf, (ki + 2) * BKT);
            loadW(nbuf, (ki + 2) * BKT);
        }
        CP_COMMIT();
    }

    // epilogue
#pragma unroll
    for (int i = 0; i < 2; i++) {
        int rA = m0 + wm * 32 + i * 16 + g;
        int rB = rA + 8;
#pragma unroll
        for (int nt = 0; nt < NT; nt++) {
            int c = cb + wn * (NT * 8) + nt * 8 + 2 * t4;
            if (c >= CO) continue;
            float b0v = 0.f, b1v = 0.f;
            if (BIAS) { b0v = B[c]; b1v = B[c + 1]; }
#pragma unroll
            for (int h2 = 0; h2 < 2; h2++) {
                int m = h2 ? rB : rA;
                if (m >= M) continue;
                float x0 = acc[i][nt][h2 * 2 + 0] + b0v;
                float x1 = acc[i][nt][h2 * 2 + 1] + b1v;
                if (ACT == 1) { x0 = siluf(x0); x1 = siluf(x1); }
                if (ACT == 2) { x0 = fmaxf(x0, 0.f); x1 = fmaxf(x1, 0.f); }
                if (OBF16) {
                    __nv_bfloat162 bv = __floats2bfloat162_rn(x0, x1);
                    uint16_t* yp16 = (uint16_t*)Y + (size_t)m * ldy + c;
                    *(uint32_t*)yp16 = *(uint32_t*)&bv;
                } else {
                    float* yp = Y + (size_t)m * ldy + c;
                    if (RESID) { float2 o = *(const float2*)yp; x0 += o.x; x1 += o.y; }
                    float2 o; o.x = x0; o.y = x1;
                    *(float2*)yp = o;
                }
            }
        }
    }

    if (ZAGG && blockIdx.y == 0) {
        float4 z = {0.f, 0.f, 0.f, 0.f};
#pragma unroll
        for (int i = 0; i < BM / 8; i++) {
            int idx = t + i * 256;
            int r = idx >> 5, c4 = (idx & 31) * 4;
            if (m0 + r < M) *(float4*)(aggz + (size_t)(m0 + r) * 128 + c4) = z;
        }
    }
}

// ---------------- fused edge layer (bf16 PQ gather) ----------------
#define TILE_E 64
#define EDGE_TILES 4
#define N_TILES (N_EDGES / TILE_E)        // 12500
#define OFF_W2S   0                        // [128][136]
#define OFF_HID   (128*136)                // [64][132]
#define OFF_WR    (OFF_HID + 64*132)
#define OFF_WE    (OFF_WR + 128)
#define OFF_B1    (OFF_WE + 128)
#define OFF_ATT   (OFF_B1 + 128)
#define OFF_B2    (OFF_ATT + 128)
#define OFF_RAD   (OFF_B2 + 128)
#define OFF_EA    (OFF_RAD + 64)
#define OFF_GPART (OFF_EA + 64)            // [64][2]
#define OFF_ROWS  (OFF_GPART + 128)
#define OFF_COLS  (OFF_ROWS + 64)
#define EDGE_SMEM ((OFF_COLS + 64) * 4)

__global__ __launch_bounds__(256) void edge_kernel(
        const __nv_bfloat16* __restrict__ PQb,
        const float* __restrict__ radial, const float* __restrict__ ea,
        const int* __restrict__ ei,
        const float* __restrict__ wr, const float* __restrict__ we,
        const float* __restrict__ b1,
        const float* __restrict__ W2, const float* __restrict__ B2,
        const float* __restrict__ attw, const float* __restrict__ attb,
        float* __restrict__ agg) {
    extern __shared__ float sm[];
    float* W2s  = sm + OFF_W2S;
    float* hid  = sm + OFF_HID;
    float* wr_s = sm + OFF_WR;
    float* we_s = sm + OFF_WE;
    float* b1_s = sm + OFF_B1;
    float* at_s = sm + OFF_ATT;
    float* b2_s = sm + OFF_B2;
    float* rd_s = sm + OFF_RAD;
    float* ea_s = sm + OFF_EA;
    float* gp_s = sm + OFF_GPART;
    int* rows_s = (int*)(sm + OFF_ROWS);
    int* cols_s = (int*)(sm + OFF_COLS);

    int t = threadIdx.x;
    int w = t >> 5, lane = t & 31;
    int g = lane >> 2, t4 = lane & 3;
    int eg0 = (w & 3) * 16, ng0 = (w >> 2) * 64;
    int wn = w >> 2;
    float attbv = attb[0];

    for (int idx = t; idx < 5 * 128; idx += 256) {
        int a = idx >> 7, c = idx & 127;
        float v;
        if (a == 0) v = wr[c];
        else if (a == 1) v = we[c];
        else if (a == 2) v = b1[c];
        else if (a == 3) v = attw[c];
        else v = B2[c];
        sm[OFF_WR + a * 128 + c] = v;
    }
    for (int idx = t; idx < 128 * 32; idx += 256) {
        int kk = idx >> 5, c4 = (idx & 31) * 4;
        *(float4*)&W2s[kk * 136 + c4] = *(const float4*)(W2 + (size_t)kk * 128 + c4);
    }

    for (int tt = 0; tt < EDGE_TILES; tt++) {
        int tile = blockIdx.x * EDGE_TILES + tt;
        if (tile >= N_TILES) break;
        int e0 = tile * TILE_E;

        __syncthreads();
        if (t < TILE_E) {
            rows_s[t] = ei[e0 + t];
            rd_s[t] = radial[e0 + t];
            ea_s[t] = ea[e0 + t];
        } else if (t < 2 * TILE_E) {
            cols_s[t - TILE_E] = ei[N_EDGES + e0 + (t - TILE_E)];
        }
        __syncthreads();

        // gather (bf16, 8 cols per 16B) + silu -> hid (fp32)
#pragma unroll
        for (int i = 0; i < 4; i++) {
            int idx = t + i * 256;
            int e = idx >> 4, c8 = (idx & 15) * 8;
            uint4 pv = *(const uint4*)(PQb + (size_t)rows_s[e] * 256 + c8);
            uint4 qv = *(const uint4*)(PQb + (size_t)cols_s[e] * 256 + 128 + c8);
            const __nv_bfloat162* pp = (const __nv_bfloat162*)&pv;
            const __nv_bfloat162* qq = (const __nv_bfloat162*)&qv;
            float rd = rd_s[e], eav = ea_s[e];
            float4 o0, o1;
            float2 p0 = __bfloat1622float2(pp[0]), q0 = __bfloat1622float2(qq[0]);
            float2 p1 = __bfloat1622float2(pp[1]), q1 = __bfloat1622float2(qq[1]);
            float2 p2 = __bfloat1622float2(pp[2]), q2 = __bfloat1622float2(qq[2]);
            float2 p3 = __bfloat1622float2(pp[3]), q3 = __bfloat1622float2(qq[3]);
            o0.x = siluf(p0.x + q0.x + rd * wr_s[c8 + 0] + eav * we_s[c8 + 0] + b1_s[c8 + 0]);
            o0.y = siluf(p0.y + q0.y + rd * wr_s[c8 + 1] + eav * we_s[c8 + 1] + b1_s[c8 + 1]);
            o0.z = siluf(p1.x + q1.x + rd * wr_s[c8 + 2] + eav * we_s[c8 + 2] + b1_s[c8 + 2]);
            o0.w = siluf(p1.y + q1.y + rd * wr_s[c8 + 3] + eav * we_s[c8 + 3] + b1_s[c8 + 3]);
            o1.x = siluf(p2.x + q2.x + rd * wr_s[c8 + 4] + eav * we_s[c8 + 4] + b1_s[c8 + 4]);
            o1.y = siluf(p2.y + q2.y + rd * wr_s[c8 + 5] + eav * we_s[c8 + 5] + b1_s[c8 + 5]);
            o1.z = siluf(p3.x + q3.x + rd * wr_s[c8 + 6] + eav * we_s[c8 + 6] + b1_s[c8 + 6]);
            o1.w = siluf(p3.y + q3.y + rd * wr_s[c8 + 7] + eav * we_s[c8 + 7] + b1_s[c8 + 7]);
            *(float4*)&hid[e * 132 + c8] = o0;
            *(float4*)&hid[e * 132 + c8 + 4] = o1;
        }
        __syncthreads();

        float acc[8][4];
#pragma unroll
        for (int nt = 0; nt < 8; nt++) { acc[nt][0] = acc[nt][1] = acc[nt][2] = acc[nt][3] = 0.f; }
#pragma unroll
        for (int k0 = 0; k0 < 128; k0 += 8) {
            uint32_t a[4];
            a[0] = f2u(hid[(eg0 + g) * 132 + k0 + t4]);
            a[1] = f2u(hid[(eg0 + g + 8) * 132 + k0 + t4]);
            a[2] = f2u(hid[(eg0 + g) * 132 + k0 + t4 + 4]);
            a[3] = f2u(hid[(eg0 + g + 8) * 132 + k0 + t4 + 4]);
#pragma unroll
            for (int nt = 0; nt < 8; nt++) {
                uint32_t b0 = f2u(W2s[(k0 + t4) * 136 + ng0 + nt * 8 + g]);
                uint32_t b1v = f2u(W2s[(k0 + t4 + 4) * 136 + ng0 + nt * 8 + g]);
                MMA8(acc[nt], a, b0, b1v);
            }
        }

        float s_a = 0.f, s_b = 0.f;
#pragma unroll
        for (int nt = 0; nt < 8; nt++) {
            int c0 = ng0 + nt * 8 + 2 * t4;
            float m0 = siluf(acc[nt][0] + b2_s[c0]);
            float m1 = siluf(acc[nt][1] + b2_s[c0 + 1]);
            float m2 = siluf(acc[nt][2] + b2_s[c0]);
            float m3 = siluf(acc[nt][3] + b2_s[c0 + 1]);
            acc[nt][0] = m0; acc[nt][1] = m1; acc[nt][2] = m2; acc[nt][3] = m3;
            s_a += m0 * at_s[c0] + m1 * at_s[c0 + 1];
            s_b += m2 * at_s[c0] + m3 * at_s[c0 + 1];
        }
        s_a += __shfl_xor_sync(0xffffffffu, s_a, 1);
        s_a += __shfl_xor_sync(0xffffffffu, s_a, 2);
        s_b += __shfl_xor_sync(0xffffffffu, s_b, 1);
        s_b += __shfl_xor_sync(0xffffffffu, s_b, 2);
        if (t4 == 0) {
            gp_s[(eg0 + g) * 2 + wn] = s_a;
            gp_s[(eg0 + g + 8) * 2 + wn] = s_b;
        }
        __syncthreads();

        {
            int ra = eg0 + g, rb = ra + 8;
            float gt_a = sigmf(gp_s[ra * 2] + gp_s[ra * 2 + 1] + attbv);
            float gt_b = sigmf(gp_s[rb * 2] + gp_s[rb * 2 + 1] + attbv);
            float* base_a = agg + (size_t)rows_s[ra] * 128 + ng0;
            float* base_b = agg + (size_t)rows_s[rb] * 128 + ng0;
            bool even = (t4 & 1) == 0;
#pragma unroll
            for (int nt = 0; nt < 8; nt++) {
                float send0 = even ? acc[nt][2] : acc[nt][0];
                float send1 = even ? acc[nt][3] : acc[nt][1];
                float rc0 = __shfl_xor_sync(0xffffffffu, send0, 1);
                float rc1 = __shfl_xor_sync(0xffffffffu, send1, 1);
                if (even) {
                    float* p = base_a + nt * 8 + 2 * t4;
                    asm volatile("red.global.add.v4.f32 [%0], {%1,%2,%3,%4};"
                                 :: "l"(p),
                                    "f"(acc[nt][0] * gt_a), "f"(acc[nt][1] * gt_a),
                                    "f"(rc0 * gt_a), "f"(rc1 * gt_a) : "memory");
                } else {
                    float* p = base_b + nt * 8 + 2 * (t4 - 1);
                    asm volatile("red.global.add.v4.f32 [%0], {%1,%2,%3,%4};"
                                 :: "l"(p),
                                    "f"(rc0 * gt_b), "f"(rc1 * gt_b),
                                    "f"(acc[nt][2] * gt_b), "f"(acc[nt][3] * gt_b) : "memory");
                }
            }
        }
    }
}

// ---------------- final head ----------------
__global__ void last2_kernel(const float* __restrict__ X, const float* __restrict__ w,
                             const float* __restrict__ b, float* __restrict__ out) {
    int gt = blockIdx.x * blockDim.x + threadIdx.x;
    int n = gt >> 5, lane = gt & 31;
    if (n >= N_NODES) return;
    float s = 0.f;
    for (int c = lane; c < 192; c += 32) s += X[(size_t)n * 192 + c] * w[c];
#pragma unroll
    for (int o = 16; o; o >>= 1) s += __shfl_down_sync(0xffffffffu, s, o);
    if (lane == 0) out[n] = sigmf(s + b[0]);
}

// ---------------- launch ----------------
extern "C" void kernel_launch(void* const* d_in, const int* in_sizes, int n_in,
                              void* d_out, int out_size) {
    const float* node_attrs = (const float*)d_in[0];
    const float* coords     = (const float*)d_in[1];
    const int*   ei         = (const int*)d_in[2];
    const float* ea         = (const float*)d_in[3];
    const float* emb_w  = (const float*)d_in[4];
    const float* emb_b  = (const float*)d_in[5];
    const float* edge_w1 = (const float*)d_in[6];
    const float* edge_b1 = (const float*)d_in[7];
    const float* edge_w2 = (const float*)d_in[8];
    const float* edge_b2 = (const float*)d_in[9];
    const float* att_w   = (const float*)d_in[10];
    const float* att_b   = (const float*)d_in[11];
    const float* node_w1 = (const float*)d_in[12];
    const float* node_b1 = (const float*)d_in[13];
    const float* node_w2 = (const float*)d_in[14];
    const float* node_b2 = (const float*)d_in[15];
    const float* dec_w1  = (const float*)d_in[16];
    const float* dec_b1  = (const float*)d_in[17];
    const float* dec_w2  = (const float*)d_in[18];
    const float* dec_b2  = (const float*)d_in[19];
    const float* ffnn_w1 = (const float*)d_in[20];
    const float* ffnn_b1 = (const float*)d_in[21];
    const float* ffnn_w2 = (const float*)d_in[22];
    const float* ffnn_b2 = (const float*)d_in[23];
    const float* last_w1 = (const float*)d_in[24];
    const float* last_b1 = (const float*)d_in[25];
    const float* last_w2 = (const float*)d_in[26];
    const float* last_b2 = (const float*)d_in[27];

    float *h, *agg, *tmp, *esmin, *h0p, *esm1, *cat, *last, *radial;
    __nv_bfloat16* PQb;
    cudaGetSymbolAddress((void**)&h, g_h);
    cudaGetSymbolAddress((void**)&PQb, g_PQb);
    cudaGetSymbolAddress((void**)&agg, g_agg);
    cudaGetSymbolAddress((void**)&tmp, g_tmp);
    cudaGetSymbolAddress((void**)&esmin, g_esmin);
    cudaGetSymbolAddress((void**)&h0p, g_h0p);
    cudaGetSymbolAddress((void**)&esm1, g_esm1);
    cudaGetSymbolAddress((void**)&cat, g_cat);
    cudaGetSymbolAddress((void**)&last, g_last);
    cudaGetSymbolAddress((void**)&radial, g_radial);

    const int S64 = GEMM_SMEM_OF(64, 2);
    const int S128 = GEMM_SMEM_OF(128, 3);

    cudaFuncSetAttribute(edge_kernel, cudaFuncAttributeMaxDynamicSharedMemorySize, EDGE_SMEM);
    cudaFuncSetAttribute(gemm_tc<128, 3, 2, false, true, 1, false, false, false>, cudaFuncAttributeMaxDynamicSharedMemorySize, S128);
    cudaFuncSetAttribute(gemm_tc<64, 2, 0, false, true, 1, false, false, false>,  cudaFuncAttributeMaxDynamicSharedMemorySize, S64);
    cudaFuncSetAttribute(gemm_tc<64, 2, 2, false, true, 1, false, false, false>,  cudaFuncAttributeMaxDynamicSharedMemorySize, S64);
    cudaFuncSetAttribute(gemm_tc<64, 2, 0, false, false, 1, true, true, true>,    cudaFuncAttributeMaxDynamicSharedMemorySize, S64);
    cudaFuncSetAttribute(gemm_tc<64, 2, 1, false, true, 3, false, false, false>,  cudaFuncAttributeMaxDynamicSharedMemorySize, S64);
    cudaFuncSetAttribute(gemm_tc<64, 2, 0, true, true, 1, false, false, false>,   cudaFuncAttributeMaxDynamicSharedMemorySize, S64);
    cudaFuncSetAttribute(gemm_tc<64, 2, 1, false, true, 1, false, false, false>,  cudaFuncAttributeMaxDynamicSharedMemorySize, S64);

    static cudaStream_t s_esm = nullptr;
    static cudaEvent_t ev0 = nullptr, ev_rad = nullptr, ev_join = nullptr;
    if (!s_esm) {
        cudaStreamCreateWithFlags(&s_esm, cudaStreamNonBlocking);
        cudaEventCreateWithFlags(&ev0, cudaEventDisableTiming);
        cudaEventCreateWithFlags(&ev_rad, cudaEventDisableTiming);
        cudaEventCreateWithFlags(&ev_join, cudaEventDisableTiming);
    }

    const int GBM = (N_NODES + 127) / 128;   // 391
    const int GB64 = (N_NODES + 63) / 64;    // 782
    const int EGB = (N_TILES + EDGE_TILES - 1) / EDGE_TILES;

    // ---- side stream: radial, then full ESM branch ----
    cudaEventRecord(ev0, 0);
    cudaStreamWaitEvent(s_esm, ev0, 0);
    radial_kernel<<<(N_EDGES + 255) / 256, 256, 0, s_esm>>>(coords, ei, radial);
    cudaEventRecord(ev_rad, s_esm);
    copy_esm<<<N_NODES, 256, 0, s_esm>>>(node_attrs, esmin);
    gemm_tc<128, 3, 2, false, true, 1, false, false, false><<<dim3(GBM, 2), 256, S128, s_esm>>>(
        esmin, nullptr, nullptr, F_ESM, 0, ffnn_w1, 256, 256, ffnn_b1, esm1, 256,
        N_NODES, F_ESM, F_ESM, 256, nullptr);
    gemm_tc<64, 2, 2, false, true, 1, false, false, false><<<dim3(GB64, 1), 256, S64, s_esm>>>(
        esm1, nullptr, nullptr, 256, 0, ffnn_w2, 64, 64, ffnn_b2, cat + 128, 192,
        N_NODES, 256, 256, 64, nullptr);
    cudaEventRecord(ev_join, s_esm);

    // ---- main chain ----
    copy_h0p<<<(N_NODES * H0P + 255) / 256, 256>>>(node_attrs, h0p);
    gemm_tc<64, 2, 0, false, true, 1, false, false, false><<<dim3(GB64, 1), 256, S64>>>(
        h0p, nullptr, nullptr, H0P, 0, emb_w, 128, 128, emb_b, h, 128,
        N_NODES, H0P, F_STRUCT, 128, nullptr);

    cudaStreamWaitEvent(0, ev_rad, 0);
    for (int i = 0; i < NLAYERS; i++) {
        const float* W1 = edge_w1 + (size_t)i * 258 * 128;
        const float* Wn = node_w1 + (size_t)i * NODE_IN * 128;
        // PQ (bf16) = h @ [W1a | W1b]; y==0 blocks also zero agg rows
        gemm_tc<64, 2, 0, false, false, 1, true, true, true><<<dim3(GB64, 2), 256, S64>>>(
            h, nullptr, nullptr, 128, 0, W1, 128, 128, nullptr, (float*)PQb, 256,
            N_NODES, 128, 128, 256, agg);
        edge_kernel<<<EGB, 256, EDGE_SMEM>>>(PQb, radial, ea, ei,
                                             W1 + 256 * 128, W1 + 257 * 128,
                                             edge_b1 + (size_t)i * 128,
                                             edge_w2 + (size_t)i * 128 * 128,
                                             edge_b2 + (size_t)i * 128,
                                             att_w + (size_t)i * 128,
                                             att_b + i, agg);
        gemm_tc<64, 2, 1, false, true, 3, false, false, false><<<dim3(GB64, 1), 256, S64>>>(
            h, agg, h0p, 128, H0P, Wn, 128, 128, node_b1 + (size_t)i * 128,
            tmp, 128, N_NODES, 352, NODE_IN, 128, nullptr);
        gemm_tc<64, 2, 0, true, true, 1, false, false, false><<<dim3(GB64, 1), 256, S64>>>(
            tmp, nullptr, nullptr, 128, 0, node_w2 + (size_t)i * 128 * 128, 128, 128,
            node_b2 + (size_t)i * 128, h, 128, N_NODES, 128, 128, 128, nullptr);
    }

    // decoder -> cat[:,0:128]
    gemm_tc<64, 2, 1, false, true, 1, false, false, false><<<dim3(GB64, 1), 256, S64>>>(
        h, nullptr, nullptr, 128, 0, dec_w1, 128, 128, dec_b1, tmp, 128,
        N_NODES, 128, 128, 128, nullptr);
    gemm_tc<64, 2, 0, false, true, 1, false, false, false><<<dim3(GB64, 1), 256, S64>>>(
        tmp, nullptr, nullptr, 128, 0, dec_w2, 128, 128, dec_b2, cat, 192,
        N_NODES, 128, 128, 128, nullptr);

    // ---- join + final head ----
    cudaStreamWaitEvent(0, ev_join, 0);
    gemm_tc<64, 2, 1, false, true, 1, false, false, false><<<dim3(GB64, 2), 256, S64>>>(
        cat, nullptr, nullptr, 192, 0, last_w1, 192, 192, last_b1, last, 192,
        N_NODES, 192, 192, 192, nullptr);
    last2_kernel<<<(N_NODES * 32 + 255) / 256, 256>>>(last, last_w2, last_b2, (float*)d_out);
}

// round 17
// speedup vs baseline: 1.4977x; 1.2781x over previous
#include <cuda_runtime.h>
#include <cuda_bf16.h>
#include <math.h>
#include <stdint.h>

#define N_NODES 50000
#define N_EDGES 800000
#define H1 128
#define F_NODE 1363
#define F_STRUCT 83
#define F_ESM 1280
#define NODE_IN 339
#define H0P 96
#define NLAYERS 4

// ---------------- scratch ----------------
__device__ float g_h[N_NODES * H1];
__device__ __nv_bfloat16 g_PQb[N_NODES * 256];
__device__ float g_agg[N_NODES * H1];
__device__ float g_tmp[N_NODES * H1];
__device__ float g_esmin[N_NODES * F_ESM];
__device__ float g_h0p[N_NODES * H0P];
__device__ float g_esm1[N_NODES * 256];
__device__ float g_cat[N_NODES * 192];
__device__ float g_last[N_NODES * 192];
__device__ float g_radial[N_EDGES];

__device__ __forceinline__ float siluf(float x) { return x / (1.f + __expf(-x)); }
__device__ __forceinline__ float sigmf(float x) { return 1.f / (1.f + __expf(-x)); }
__device__ __forceinline__ uint32_t f2u(float x) { return __float_as_uint(x); }
__device__ __forceinline__ uint32_t pk2(float a, float b) {
    __nv_bfloat162 v = __floats2bfloat162_rn(a, b);
    return *(uint32_t*)&v;
}

#define MMA8(d, a, b0, b1)                                                    \
    asm volatile(                                                             \
        "mma.sync.aligned.m16n8k8.row.col.f32.tf32.tf32.f32 "                 \
        "{%0,%1,%2,%3}, {%4,%5,%6,%7}, {%8,%9}, {%0,%1,%2,%3};"               \
        : "+f"(d[0]), "+f"(d[1]), "+f"(d[2]), "+f"(d[3])                      \
        : "r"(a[0]), "r"(a[1]), "r"(a[2]), "r"(a[3]), "r"(b0), "r"(b1))

#define MMA16(d, a, b0, b1)                                                   \
    asm volatile(                                                             \
        "mma.sync.aligned.m16n8k16.row.col.f32.bf16.bf16.f32 "                \
        "{%0,%1,%2,%3}, {%4,%5,%6,%7}, {%8,%9}, {%0,%1,%2,%3};"               \
        : "+f"(d[0]), "+f"(d[1]), "+f"(d[2]), "+f"(d[3])                      \
        : "r"(a[0]), "r"(a[1]), "r"(a[2]), "r"(a[3]), "r"(b0), "r"(b1))

__device__ __forceinline__ void cp_async16(uint32_t dst, const void* src, int sz) {
    asm volatile("cp.async.cg.shared.global [%0], [%1], 16, %2;"
                 :: "r"(dst), "l"(src), "r"(sz));
}
#define CP_COMMIT() asm volatile("cp.async.commit_group;")
template <int NW>
__device__ __forceinline__ void cp_wait() {
    asm volatile("cp.async.wait_group %0;" :: "n"(NW));
}

// ---------------- radial ----------------
__global__ void radial_kernel(const float* __restrict__ coords,
                              const int* __restrict__ ei,
                              float* __restrict__ radial) {
    int e = blockIdx.x * blockDim.x + threadIdx.x;
    if (e >= N_EDGES) return;
    int r = ei[e], c = ei[N_EDGES + e];
    float dx = coords[r * 3 + 0] - coords[c * 3 + 0];
    float dy = coords[r * 3 + 1] - coords[c * 3 + 1];
    float dz = coords[r * 3 + 2] - coords[c * 3 + 2];
    radial[e] = dx * dx + dy * dy + dz * dz;
}

// ---------------- input staging ----------------
__global__ void copy_h0p(const float* __restrict__ na, float* __restrict__ h0p) {
    int idx = blockIdx.x * blockDim.x + threadIdx.x;
    if (idx >= N_NODES * H0P) return;
    int n = idx / H0P, c = idx % H0P;
    h0p[idx] = (c < F_STRUCT) ? na[(size_t)n * F_NODE + c] : 0.f;
}
__global__ void copy_esm(const float* __restrict__ na, float* __restrict__ esmd) {
    int n = blockIdx.x, t = threadIdx.x;
    const float* src = na + (size_t)n * F_NODE + F_STRUCT;
#pragma unroll
    for (int c = t; c < F_ESM; c += 256) esmd[(size_t)n * F_ESM + c] = src[c];
}

// ---------------- shared tile constants ----------------
#define BKT 32
#define AS_STRIDE 36
#define WS_STRIDE 136
#define WS_SZ (BKT * WS_STRIDE)
#define GEMM_SMEM_OF(BM, STG) (((BM) * AS_STRIDE + WS_SZ) * (STG) * 4)

// ---------------- async pipelined tf32 GEMM ----------------
template <int BM, int STG, int ACT, bool RESID, bool BIAS, int NX, bool WSPLIT,
          bool ZAGG, bool OBF16>
__global__ __launch_bounds__(256) void gemm_tc(
        const float* __restrict__ X, const float* __restrict__ X2,
        const float* __restrict__ X3, int ldx, int ldx3,
        const float* __restrict__ W, int ldw, int COw,
        const float* __restrict__ B,
        float* __restrict__ Y, int ldy,
        int M, int K, int KW, int CO,
        float* __restrict__ aggz) {
    constexpr int WM = BM / 32;
    constexpr int NT = 2 * WM;
    constexpr int AS_SZ = BM * AS_STRIDE;
    constexpr int STAGE_SZ = AS_SZ + WS_SZ;

    extern __shared__ float smn[];
    uint32_t sm_u = (uint32_t)__cvta_generic_to_shared(smn);

    int t = threadIdx.x;
    int warp = t >> 5, lane = t & 31;
    int g = lane >> 2, t4 = lane & 3;
    int wm = warp % WM, wn = warp / WM;
    int m0 = blockIdx.x * BM, cb = blockIdx.y * 128;

    const float* Wbase = WSPLIT ? (W + (size_t)blockIdx.y * 128 * 128) : W;
    int cw = WSPLIT ? 0 : cb;

    float acc[2][NT][4];
#pragma unroll
    for (int i = 0; i < 2; i++)
#pragma unroll
        for (int nt = 0; nt < NT; nt++)
            acc[i][nt][0] = acc[i][nt][1] = acc[i][nt][2] = acc[i][nt][3] = 0.f;

    auto loadA = [&](int buf, int k0) {
        const float* Xs = X; int kb = k0, ld = ldx;
        if (NX >= 3 && k0 >= 256)      { Xs = X3; kb = k0 - 256; ld = ldx3; }
        else if (NX >= 2 && k0 >= 128) { Xs = X2; kb = k0 - 128; }
#pragma unroll
        for (int i = 0; i < BM / 32; i++) {
            int idx = t + i * 256;
            int r = idx >> 3, c4 = (idx & 7) * 4;
            uint32_t dst = sm_u + (buf * STAGE_SZ + r * AS_STRIDE + c4) * 4;
            const float* src = Xs + (size_t)(m0 + r) * ld + kb + c4;
            cp_async16(dst, src, (m0 + r < M) ? 16 : 0);
        }
    };
    auto loadW = [&](int buf, int k0) {
#pragma unroll
        for (int i = 0; i < 4; i++) {
            int idx = t + i * 256;
            int kk = idx >> 5, c4 = (idx & 31) * 4;
            uint32_t dst = sm_u + (buf * STAGE_SZ + AS_SZ + kk * WS_STRIDE + c4) * 4;
            const float* src = Wbase + (size_t)(k0 + kk) * ldw + cw + c4;
            cp_async16(dst, src, (k0 + kk < KW && cw + c4 < COw) ? 16 : 0);
        }
    };

    int nk = K / BKT;
    loadA(0, 0); loadW(0, 0); CP_COMMIT();
    if (nk > 1) { loadA(1 % STG, BKT); loadW(1 % STG, BKT); }
    CP_COMMIT();

    for (int ki = 0; ki < nk; ki++) {
        int buf = ki % STG;
        cp_wait<1>();
        __syncthreads();
        const float* A = smn + buf * STAGE_SZ;
        const float* Wb = A + AS_SZ;
#pragma unroll
        for (int ks = 0; ks < BKT; ks += 8) {
            uint32_t a[2][4];
#pragma unroll
            for (int i = 0; i < 2; i++) {
                int r = wm * 32 + i * 16 + g;
                a[i][0] = f2u(A[r * AS_STRIDE + ks + t4]);
                a[i][1] = f2u(A[(r + 8) * AS_STRIDE + ks + t4]);
                a[i][2] = f2u(A[r * AS_STRIDE + ks + t4 + 4]);
                a[i][3] = f2u(A[(r + 8) * AS_STRIDE + ks + t4 + 4]);
            }
#pragma unroll
            for (int nt = 0; nt < NT; nt++) {
                int c = wn * (NT * 8) + nt * 8 + g;
                uint32_t b0 = f2u(Wb[(ks + t4) * WS_STRIDE + c]);
                uint32_t b1 = f2u(Wb[(ks + t4 + 4) * WS_STRIDE + c]);
                MMA8(acc[0][nt], a[0], b0, b1);
                MMA8(acc[1][nt], a[1], b0, b1);
            }
        }
        __syncthreads();
        if (ki + 2 < nk) {
            int nbuf = (ki + 2) % STG;
            loadA(nbuf, (ki + 2) * BKT);
            loadW(nbuf, (ki + 2) * BKT);
        }
        CP_COMMIT();
    }

    // epilogue
#pragma unroll
    for (int i = 0; i < 2; i++) {
        int rA = m0 + wm * 32 + i * 16 + g;
        int rB = rA + 8;
#pragma unroll
        for (int nt = 0; nt < NT; nt++) {
            int c = cb + wn * (NT * 8) + nt * 8 + 2 * t4;
            if (c >= CO) continue;
            float b0v = 0.f, b1v = 0.f;
            if (BIAS) { b0v = B[c]; b1v = B[c + 1]; }
#pragma unroll
            for (int h2 = 0; h2 < 2; h2++) {
                int m = h2 ? rB : rA;
                if (m >= M) continue;
                float x0 = acc[i][nt][h2 * 2 + 0] + b0v;
                float x1 = acc[i][nt][h2 * 2 + 1] + b1v;
                if (ACT == 1) { x0 = siluf(x0); x1 = siluf(x1); }
                if (ACT == 2) { x0 = fmaxf(x0, 0.f); x1 = fmaxf(x1, 0.f); }
                if (OBF16) {
                    uint16_t* yp16 = (uint16_t*)Y + (size_t)m * ldy + c;
                    *(uint32_t*)yp16 = pk2(x0, x1);
                } else {
                    float* yp = Y + (size_t)m * ldy + c;
                    if (RESID) { float2 o = *(const float2*)yp; x0 += o.x; x1 += o.y; }
                    float2 o; o.x = x0; o.y = x1;
                    *(float2*)yp = o;
                }
            }
        }
    }

    if (ZAGG && blockIdx.y == 0) {
        float4 z = {0.f, 0.f, 0.f, 0.f};
#pragma unroll
        for (int i = 0; i < BM / 8; i++) {
            int idx = t + i * 256;
            int r = idx >> 5, c4 = (idx & 31) * 4;
            if (m0 + r < M) *(float4*)(aggz + (size_t)(m0 + r) * 128 + c4) = z;
        }
    }
}

// ---------------- fused edge layer: bf16 MMA (m16n8k16) ----------------
#define TILE_E 64
#define EDGE_TILES 4
#define N_TILES (N_EDGES / TILE_E)        // 12500
// u32-indexed smem layout
#define OFF_W2P   0                        // [128 cols][68] packed bf16x2 (k-pairs)
#define OFF_HIDP  (128*68)                 // [64 edges][68] packed bf16x2
#define OFF_WR    (OFF_HIDP + 64*68)
#define OFF_WE    (OFF_WR + 128)
#define OFF_B1    (OFF_WE + 128)
#define OFF_ATT   (OFF_B1 + 128)
#define OFF_B2    (OFF_ATT + 128)
#define OFF_RAD   (OFF_B2 + 128)
#define OFF_EA    (OFF_RAD + 64)
#define OFF_GPART (OFF_EA + 64)
#define OFF_ROWS  (OFF_GPART + 128)
#define OFF_COLS  (OFF_ROWS + 64)
#define EDGE_SMEM ((OFF_COLS + 64) * 4)

__global__ __launch_bounds__(256) void edge_kernel(
        const __nv_bfloat16* __restrict__ PQb,
        const float* __restrict__ radial, const float* __restrict__ ea,
        const int* __restrict__ ei,
        const float* __restrict__ wr, const float* __restrict__ we,
        const float* __restrict__ b1,
        const float* __restrict__ W2, const float* __restrict__ B2,
        const float* __restrict__ attw, const float* __restrict__ attb,
        float* __restrict__ agg) {
    extern __shared__ float sm[];
    uint32_t* W2p  = (uint32_t*)sm + OFF_W2P;
    uint32_t* hidp = (uint32_t*)sm + OFF_HIDP;
    float* wr_s = sm + OFF_WR;
    float* we_s = sm + OFF_WE;
    float* b1_s = sm + OFF_B1;
    float* at_s = sm + OFF_ATT;
    float* b2_s = sm + OFF_B2;
    float* rd_s = sm + OFF_RAD;
    float* ea_s = sm + OFF_EA;
    float* gp_s = sm + OFF_GPART;
    int* rows_s = (int*)(sm + OFF_ROWS);
    int* cols_s = (int*)(sm + OFF_COLS);

    int t = threadIdx.x;
    int w = t >> 5, lane = t & 31;
    int g = lane >> 2, t4 = lane & 3;
    int eg0 = (w & 3) * 16, ng0 = (w >> 2) * 64;
    int wn = w >> 2;
    float attbv = attb[0];

    for (int idx = t; idx < 5 * 128; idx += 256) {
        int a = idx >> 7, c = idx & 127;
        float v;
        if (a == 0) v = wr[c];
        else if (a == 1) v = we[c];
        else if (a == 2) v = b1[c];
        else if (a == 3) v = attw[c];
        else v = B2[c];
        sm[OFF_WR + a * 128 + c] = v;
    }
    // stage W2 transposed+packed: W2p[c*68 + kp] = bf16x2(W2[2kp][c], W2[2kp+1][c])
    for (int idx = t; idx < 64 * 128; idx += 256) {
        int kp = idx >> 7, c = idx & 127;
        float w0 = W2[(size_t)(2 * kp) * 128 + c];
        float w1 = W2[(size_t)(2 * kp + 1) * 128 + c];
        W2p[c * 68 + kp] = pk2(w0, w1);
    }

    for (int tt = 0; tt < EDGE_TILES; tt++) {
        int tile = blockIdx.x * EDGE_TILES + tt;
        if (tile >= N_TILES) break;
        int e0 = tile * TILE_E;

        __syncthreads();
        if (t < TILE_E) {
            rows_s[t] = ei[e0 + t];
            rd_s[t] = radial[e0 + t];
            ea_s[t] = ea[e0 + t];
        } else if (t < 2 * TILE_E) {
            cols_s[t - TILE_E] = ei[N_EDGES + e0 + (t - TILE_E)];
        }
        __syncthreads();

        // gather (bf16 PQ) + silu -> hidp (packed bf16x2)
#pragma unroll
        for (int i = 0; i < 4; i++) {
            int idx = t + i * 256;
            int e = idx >> 4, c8 = (idx & 15) * 8;
            uint4 pv = *(const uint4*)(PQb + (size_t)rows_s[e] * 256 + c8);
            uint4 qv = *(const uint4*)(PQb + (size_t)cols_s[e] * 256 + 128 + c8);
            const __nv_bfloat162* pp = (const __nv_bfloat162*)&pv;
            const __nv_bfloat162* qq = (const __nv_bfloat162*)&qv;
            float rd = rd_s[e], eav = ea_s[e];
            float2 p0 = __bfloat1622float2(pp[0]), q0 = __bfloat1622float2(qq[0]);
            float2 p1 = __bfloat1622float2(pp[1]), q1 = __bfloat1622float2(qq[1]);
            float2 p2 = __bfloat1622float2(pp[2]), q2 = __bfloat1622float2(qq[2]);
            float2 p3 = __bfloat1622float2(pp[3]), q3 = __bfloat1622float2(qq[3]);
            float o0 = siluf(p0.x + q0.x + rd * wr_s[c8 + 0] + eav * we_s[c8 + 0] + b1_s[c8 + 0]);
            float o1 = siluf(p0.y + q0.y + rd * wr_s[c8 + 1] + eav * we_s[c8 + 1] + b1_s[c8 + 1]);
            float o2 = siluf(p1.x + q1.x + rd * wr_s[c8 + 2] + eav * we_s[c8 + 2] + b1_s[c8 + 2]);
            float o3 = siluf(p1.y + q1.y + rd * wr_s[c8 + 3] + eav * we_s[c8 + 3] + b1_s[c8 + 3]);
            float o4 = siluf(p2.x + q2.x + rd * wr_s[c8 + 4] + eav * we_s[c8 + 4] + b1_s[c8 + 4]);
            float o5 = siluf(p2.y + q2.y + rd * wr_s[c8 + 5] + eav * we_s[c8 + 5] + b1_s[c8 + 5]);
            float o6 = siluf(p3.x + q3.x + rd * wr_s[c8 + 6] + eav * we_s[c8 + 6] + b1_s[c8 + 6]);
            float o7 = siluf(p3.y + q3.y + rd * wr_s[c8 + 7] + eav * we_s[c8 + 7] + b1_s[c8 + 7]);
            uint4 pkv;
            pkv.x = pk2(o0, o1); pkv.y = pk2(o2, o3);
            pkv.z = pk2(o4, o5); pkv.w = pk2(o6, o7);
            *(uint4*)&hidp[e * 68 + (idx & 15) * 4] = pkv;
        }
        __syncthreads();

        // GEMM2: bf16 m16n8k16, 8 k-iterations
        float acc[8][4];
#pragma unroll
        for (int nt = 0; nt < 8; nt++) { acc[nt][0] = acc[nt][1] = acc[nt][2] = acc[nt][3] = 0.f; }
#pragma unroll
        for (int k0 = 0; k0 < 128; k0 += 16) {
            int kp = k0 >> 1;
            uint32_t a[4];
            a[0] = hidp[(eg0 + g) * 68 + kp + t4];
            a[1] = hidp[(eg0 + g + 8) * 68 + kp + t4];
            a[2] = hidp[(eg0 + g) * 68 + kp + t4 + 4];
            a[3] = hidp[(eg0 + g + 8) * 68 + kp + t4 + 4];
#pragma unroll
            for (int nt = 0; nt < 8; nt++) {
                int c = ng0 + nt * 8 + g;
                uint32_t b0 = W2p[c * 68 + kp + t4];
                uint32_t b1v = W2p[c * 68 + kp + t4 + 4];
                MMA16(acc[nt], a, b0, b1v);
            }
        }

        // register epilogue: m = silu(acc+b2); fused gate partials
        float s_a = 0.f, s_b = 0.f;
#pragma unroll
        for (int nt = 0; nt < 8; nt++) {
            int c0 = ng0 + nt * 8 + 2 * t4;
            float m0 = siluf(acc[nt][0] + b2_s[c0]);
            float m1 = siluf(acc[nt][1] + b2_s[c0 + 1]);
            float m2 = siluf(acc[nt][2] + b2_s[c0]);
            float m3 = siluf(acc[nt][3] + b2_s[c0 + 1]);
            acc[nt][0] = m0; acc[nt][1] = m1; acc[nt][2] = m2; acc[nt][3] = m3;
            s_a += m0 * at_s[c0] + m1 * at_s[c0 + 1];
            s_b += m2 * at_s[c0] + m3 * at_s[c0 + 1];
        }
        s_a += __shfl_xor_sync(0xffffffffu, s_a, 1);
        s_a += __shfl_xor_sync(0xffffffffu, s_a, 2);
        s_b += __shfl_xor_sync(0xffffffffu, s_b, 1);
        s_b += __shfl_xor_sync(0xffffffffu, s_b, 2);
        if (t4 == 0) {
            gp_s[(eg0 + g) * 2 + wn] = s_a;
            gp_s[(eg0 + g + 8) * 2 + wn] = s_b;
        }
        __syncthreads();

        // gate + scatter from registers (pair-exchange keeps red.v4)
        {
            int ra = eg0 + g, rb = ra + 8;
            float gt_a = sigmf(gp_s[ra * 2] + gp_s[ra * 2 + 1] + attbv);
            float gt_b = sigmf(gp_s[rb * 2] + gp_s[rb * 2 + 1] + attbv);
            float* base_a = agg + (size_t)rows_s[ra] * 128 + ng0;
            float* base_b = agg + (size_t)rows_s[rb] * 128 + ng0;
            bool even = (t4 & 1) == 0;
#pragma unroll
            for (int nt = 0; nt < 8; nt++) {
                float send0 = even ? acc[nt][2] : acc[nt][0];
                float send1 = even ? acc[nt][3] : acc[nt][1];
                float rc0 = __shfl_xor_sync(0xffffffffu, send0, 1);
                float rc1 = __shfl_xor_sync(0xffffffffu, send1, 1);
                if (even) {
                    float* p = base_a + nt * 8 + 2 * t4;
                    asm volatile("red.global.add.v4.f32 [%0], {%1,%2,%3,%4};"
                                 :: "l"(p),
                                    "f"(acc[nt][0] * gt_a), "f"(acc[nt][1] * gt_a),
                                    "f"(rc0 * gt_a), "f"(rc1 * gt_a) : "memory");
                } else {
                    float* p = base_b + nt * 8 + 2 * (t4 - 1);
                    asm volatile("red.global.add.v4.f32 [%0], {%1,%2,%3,%4};"
                                 :: "l"(p),
                                    "f"(rc0 * gt_b), "f"(rc1 * gt_b),
                                    "f"(acc[nt][2] * gt_b), "f"(acc[nt][3] * gt_b) : "memory");
                }
            }
        }
    }
}

// ---------------- final head ----------------
__global__ void last2_kernel(const float* __restrict__ X, const float* __restrict__ w,
                             const float* __restrict__ b, float* __restrict__ out) {
    int gt = blockIdx.x * blockDim.x + threadIdx.x;
    int n = gt >> 5, lane = gt & 31;
    if (n >= N_NODES) return;
    float s = 0.f;
    for (int c = lane; c < 192; c += 32) s += X[(size_t)n * 192 + c] * w[c];
#pragma unroll
    for (int o = 16; o; o >>= 1) s += __shfl_down_sync(0xffffffffu, s, o);
    if (lane == 0) out[n] = sigmf(s + b[0]);
}

// ---------------- launch ----------------
extern "C" void kernel_launch(void* const* d_in, const int* in_sizes, int n_in,
                              void* d_out, int out_size) {
    const float* node_attrs = (const float*)d_in[0];
    const float* coords     = (const float*)d_in[1];
    const int*   ei         = (const int*)d_in[2];
    const float* ea         = (const float*)d_in[3];
    const float* emb_w  = (const float*)d_in[4];
    const float* emb_b  = (const float*)d_in[5];
    const float* edge_w1 = (const float*)d_in[6];
    const float* edge_b1 = (const float*)d_in[7];
    const float* edge_w2 = (const float*)d_in[8];
    const float* edge_b2 = (const float*)d_in[9];
    const float* att_w   = (const float*)d_in[10];
    const float* att_b   = (const float*)d_in[11];
    const float* node_w1 = (const float*)d_in[12];
    const float* node_b1 = (const float*)d_in[13];
    const float* node_w2 = (const float*)d_in[14];
    const float* node_b2 = (const float*)d_in[15];
    const float* dec_w1  = (const float*)d_in[16];
    const float* dec_b1  = (const float*)d_in[17];
    const float* dec_w2  = (const float*)d_in[18];
    const float* dec_b2  = (const float*)d_in[19];
    const float* ffnn_w1 = (const float*)d_in[20];
    const float* ffnn_b1 = (const float*)d_in[21];
    const float* ffnn_w2 = (const float*)d_in[22];
    const float* ffnn_b2 = (const float*)d_in[23];
    const float* last_w1 = (const float*)d_in[24];
    const float* last_b1 = (const float*)d_in[25];
    const float* last_w2 = (const float*)d_in[26];
    const float* last_b2 = (const float*)d_in[27];

    float *h, *agg, *tmp, *esmin, *h0p, *esm1, *cat, *last, *radial;
    __nv_bfloat16* PQb;
    cudaGetSymbolAddress((void**)&h, g_h);
    cudaGetSymbolAddress((void**)&PQb, g_PQb);
    cudaGetSymbolAddress((void**)&agg, g_agg);
    cudaGetSymbolAddress((void**)&tmp, g_tmp);
    cudaGetSymbolAddress((void**)&esmin, g_esmin);
    cudaGetSymbolAddress((void**)&h0p, g_h0p);
    cudaGetSymbolAddress((void**)&esm1, g_esm1);
    cudaGetSymbolAddress((void**)&cat, g_cat);
    cudaGetSymbolAddress((void**)&last, g_last);
    cudaGetSymbolAddress((void**)&radial, g_radial);

    const int S64 = GEMM_SMEM_OF(64, 2);
    const int S128 = GEMM_SMEM_OF(128, 3);

    cudaFuncSetAttribute(edge_kernel, cudaFuncAttributeMaxDynamicSharedMemorySize, EDGE_SMEM);
    cudaFuncSetAttribute(gemm_tc<128, 3, 2, false, true, 1, false, false, false>, cudaFuncAttributeMaxDynamicSharedMemorySize, S128);
    cudaFuncSetAttribute(gemm_tc<64, 2, 0, false, true, 1, false, false, false>,  cudaFuncAttributeMaxDynamicSharedMemorySize, S64);
    cudaFuncSetAttribute(gemm_tc<64, 2, 2, false, true, 1, false, false, false>,  cudaFuncAttributeMaxDynamicSharedMemorySize, S64);
    cudaFuncSetAttribute(gemm_tc<64, 2, 0, false, false, 1, true, true, true>,    cudaFuncAttributeMaxDynamicSharedMemorySize, S64);
    cudaFuncSetAttribute(gemm_tc<64, 2, 1, false, true, 3, false, false, false>,  cudaFuncAttributeMaxDynamicSharedMemorySize, S64);
    cudaFuncSetAttribute(gemm_tc<64, 2, 0, true, true, 1, false, false, false>,   cudaFuncAttributeMaxDynamicSharedMemorySize, S64);
    cudaFuncSetAttribute(gemm_tc<64, 2, 1, false, true, 1, false, false, false>,  cudaFuncAttributeMaxDynamicSharedMemorySize, S64);

    static cudaStream_t s_esm = nullptr;
    static cudaEvent_t ev0 = nullptr, ev_rad = nullptr, ev_join = nullptr;
    if (!s_esm) {
        cudaStreamCreateWithFlags(&s_esm, cudaStreamNonBlocking);
        cudaEventCreateWithFlags(&ev0, cudaEventDisableTiming);
        cudaEventCreateWithFlags(&ev_rad, cudaEventDisableTiming);
        cudaEventCreateWithFlags(&ev_join, cudaEventDisableTiming);
    }

    const int GBM = (N_NODES + 127) / 128;   // 391
    const int GB64 = (N_NODES + 63) / 64;    // 782
    const int EGB = (N_TILES + EDGE_TILES - 1) / EDGE_TILES;

    // ---- side stream: radial, then full ESM branch ----
    cudaEventRecord(ev0, 0);
    cudaStreamWaitEvent(s_esm, ev0, 0);
    radial_kernel<<<(N_EDGES + 255) / 256, 256, 0, s_esm>>>(coords, ei, radial);
    cudaEventRecord(ev_rad, s_esm);
    copy_esm<<<N_NODES, 256, 0, s_esm>>>(node_attrs, esmin);
    gemm_tc<128, 3, 2, false, true, 1, false, false, false><<<dim3(GBM, 2), 256, S128, s_esm>>>(
        esmin, nullptr, nullptr, F_ESM, 0, ffnn_w1, 256, 256, ffnn_b1, esm1, 256,
        N_NODES, F_ESM, F_ESM, 256, nullptr);
    gemm_tc<64, 2, 2, false, true, 1, false, false, false><<<dim3(GB64, 1), 256, S64, s_esm>>>(
        esm1, nullptr, nullptr, 256, 0, ffnn_w2, 64, 64, ffnn_b2, cat + 128, 192,
        N_NODES, 256, 256, 64, nullptr);
    cudaEventRecord(ev_join, s_esm);

    // ---- main chain ----
    copy_h0p<<<(N_NODES * H0P + 255) / 256, 256>>>(node_attrs, h0p);
    gemm_tc<64, 2, 0, false, true, 1, false, false, false><<<dim3(GB64, 1), 256, S64>>>(
        h0p, nullptr, nullptr, H0P, 0, emb_w, 128, 128, emb_b, h, 128,
        N_NODES, H0P, F_STRUCT, 128, nullptr);

    cudaStreamWaitEvent(0, ev_rad, 0);
    for (int i = 0; i < NLAYERS; i++) {
        const float* W1 = edge_w1 + (size_t)i * 258 * 128;
        const float* Wn = node_w1 + (size_t)i * NODE_IN * 128;
        gemm_tc<64, 2, 0, false, false, 1, true, true, true><<<dim3(GB64, 2), 256, S64>>>(
            h, nullptr, nullptr, 128, 0, W1, 128, 128, nullptr, (float*)PQb, 256,
            N_NODES, 128, 128, 256, agg);
        edge_kernel<<<EGB, 256, EDGE_SMEM>>>(PQb, radial, ea, ei,
                                             W1 + 256 * 128, W1 + 257 * 128,
                                             edge_b1 + (size_t)i * 128,
                                             edge_w2 + (size_t)i * 128 * 128,
                                             edge_b2 + (size_t)i * 128,
                                             att_w + (size_t)i * 128,
                                             att_b + i, agg);
        gemm_tc<64, 2, 1, false, true, 3, false, false, false><<<dim3(GB64, 1), 256, S64>>>(
            h, agg, h0p, 128, H0P, Wn, 128, 128, node_b1 + (size_t)i * 128,
            tmp, 128, N_NODES, 352, NODE_IN, 128, nullptr);
        gemm_tc<64, 2, 0, true, true, 1, false, false, false><<<dim3(GB64, 1), 256, S64>>>(
            tmp, nullptr, nullptr, 128, 0, node_w2 + (size_t)i * 128 * 128, 128, 128,
            node_b2 + (size_t)i * 128, h, 128, N_NODES, 128, 128, 128, nullptr);
    }

    // decoder -> cat[:,0:128]
    gemm_tc<64, 2, 1, false, true, 1, false, false, false><<<dim3(GB64, 1), 256, S64>>>(
        h, nullptr, nullptr, 128, 0, dec_w1, 128, 128, dec_b1, tmp, 128,
        N_NODES, 128, 128, 128, nullptr);
    gemm_tc<64, 2, 0, false, true, 1, false, false, false><<<dim3(GB64, 1), 256, S64>>>(
        tmp, nullptr, nullptr, 128, 0, dec_w2, 128, 128, dec_b2, cat, 192,
        N_NODES, 128, 128, 128, nullptr);

    // ---- join + final head ----
    cudaStreamWaitEvent(0, ev_join, 0);
    gemm_tc<64, 2, 1, false, true, 1, false, false, false><<<dim3(GB64, 2), 256, S64>>>(
        cat, nullptr, nullptr, 192, 0, last_w1, 192, 192, last_b1, last, 192,
        N_NODES, 192, 192, 192, nullptr);
    last2_kernel<<<(N_NODES * 32 + 255) / 256, 256>>>(last, last_w2, last_b2, (float*)d_out);
}